// round 1
// baseline (speedup 1.0000x reference)
#include <cuda_runtime.h>
#include <cuda_bf16.h>
#include <math.h>

// Problem constants
#define BB   4
#define SS   2048
#define HD   1024
#define NHH  16
#define DD   64
#define FFD  4096
#define BSR  (BB*SS)          // 8192 rows

// ---------------- scratch (device globals: no allocation allowed) ----------
__device__ float g_q  [BSR * HD];
__device__ float g_k  [BSR * HD];
__device__ float g_v  [BSR * HD];
__device__ float g_ctx[BSR * HD];
__device__ float g_r1 [BSR * HD];
__device__ float g_h  [BSR * HD];
__device__ float g_ff [BSR * FFD];
__device__ float g_r2 [BSR * HD];

// ---------------- GEMM: C[M,N] = A[M,K] @ B[K,N] + bias (+add) (opt gelu) --
// BM=BN=128, BK=8, TM=TN=8, 256 threads.
template<int EPI>   // 0 = none, 1 = gelu(tanh approx)
__global__ __launch_bounds__(256)
void gemm_kernel(const float* __restrict__ A, const float* __restrict__ B,
                 const float* __restrict__ bias, const float* __restrict__ add,
                 float* __restrict__ C, int M, int N, int K)
{
    const int BM = 128, BN = 128, BK = 8, TM = 8, TN = 8;
    __shared__ float As[BK][BM];
    __shared__ float Bs[BK][BN];

    const int tid  = threadIdx.x;
    const int crow = blockIdx.y * BM;
    const int ccol = blockIdx.x * BN;

    const int tr = (tid / 16) * TM;      // 0..120
    const int tc = (tid % 16) * TN;      // 0..120

    // A tile: 128 rows x 8 cols -> 256 float4 loads
    const int arow = tid >> 1;           // 0..127
    const int acol = (tid & 1) * 4;      // 0 or 4
    // B tile: 8 rows x 128 cols -> 256 float4 loads
    const int brow = tid >> 5;           // 0..7
    const int bcol = (tid & 31) * 4;     // 0..124

    float acc[TM][TN];
    #pragma unroll
    for (int i = 0; i < TM; i++)
        #pragma unroll
        for (int j = 0; j < TN; j++) acc[i][j] = 0.f;

    const float* Aptr = A + (size_t)(crow + arow) * K + acol;
    const float* Bptr = B + (size_t)brow * N + ccol + bcol;

    for (int k0 = 0; k0 < K; k0 += BK) {
        float4 av = *(const float4*)(Aptr + k0);
        float4 bv = *(const float4*)(Bptr + (size_t)k0 * N);
        As[acol + 0][arow] = av.x;
        As[acol + 1][arow] = av.y;
        As[acol + 2][arow] = av.z;
        As[acol + 3][arow] = av.w;
        *(float4*)&Bs[brow][bcol] = bv;
        __syncthreads();

        #pragma unroll
        for (int k = 0; k < BK; k++) {
            float ra[TM], rb[TN];
            float4 a0 = *(const float4*)&As[k][tr];
            float4 a1 = *(const float4*)&As[k][tr + 4];
            ra[0]=a0.x; ra[1]=a0.y; ra[2]=a0.z; ra[3]=a0.w;
            ra[4]=a1.x; ra[5]=a1.y; ra[6]=a1.z; ra[7]=a1.w;
            float4 b0 = *(const float4*)&Bs[k][tc];
            float4 b1 = *(const float4*)&Bs[k][tc + 4];
            rb[0]=b0.x; rb[1]=b0.y; rb[2]=b0.z; rb[3]=b0.w;
            rb[4]=b1.x; rb[5]=b1.y; rb[6]=b1.z; rb[7]=b1.w;
            #pragma unroll
            for (int i = 0; i < TM; i++)
                #pragma unroll
                for (int j = 0; j < TN; j++)
                    acc[i][j] = fmaf(ra[i], rb[j], acc[i][j]);
        }
        __syncthreads();
    }

    // epilogue
    #pragma unroll
    for (int i = 0; i < TM; i++) {
        const int r = crow + tr + i;
        #pragma unroll
        for (int j = 0; j < TN; j++) {
            const int c = ccol + tc + j;
            float v = acc[i][j] + bias[c];
            if (add) v += add[(size_t)r * N + c];
            if (EPI == 1) {
                float u = v;
                v = 0.5f * u * (1.f + tanhf(0.7978845608028654f * (u + 0.044715f * u * u * u)));
            }
            C[(size_t)r * N + c] = v;
        }
    }
}

// ---------------- RoPE (in-place on q,k in [BS, Hd] layout) ----------------
__global__ __launch_bounds__(256)
void rope_kernel(float* __restrict__ q, float* __restrict__ k)
{
    const int idx = blockIdx.x * blockDim.x + threadIdx.x;   // one pair
    if (idx >= BSR * (HD / 2)) return;
    const int row = idx >> 9;            // /512 pairs per row
    const int p   = idx & 511;
    const int s   = row & (SS - 1);      // position within sequence
    const int i   = p & 31;              // pair index within head (D/2 = 32)

    const double e   = -((double)(2 * i)) / 64.0;
    const float  inv = (float)pow(10000.0, e);
    const float  ang = (float)s * inv;
    const float  c  = cosf(ang);
    const float  sn = sinf(ang);

    float2* qp = (float2*)(q + (size_t)row * HD) + p;
    float2* kp = (float2*)(k + (size_t)row * HD) + p;
    float2 qv = *qp, kv = *kp;
    float2 qo, ko;
    qo.x = qv.x * c - qv.y * sn;  qo.y = qv.y * c + qv.x * sn;
    ko.x = kv.x * c - kv.y * sn;  ko.y = kv.y * c + kv.x * sn;
    *qp = qo; *kp = ko;
}

// ---------------- Flash attention -----------------------------------------
// grid: (S/128, B*NH); 128 threads, one q-row per thread; 64-row K/V tiles.
__global__ __launch_bounds__(128)
void attn_kernel(const float* __restrict__ Q, const float* __restrict__ Kg,
                 const float* __restrict__ Vg, float* __restrict__ O)
{
    __shared__ float Ks[64][64];
    __shared__ float Vs[64][64];

    const int bh = blockIdx.y;
    const int b  = bh >> 4;
    const int h  = bh & 15;
    const int qs = blockIdx.x * 128 + threadIdx.x;
    const float scale = 0.125f;  // 1/sqrt(64)

    float qr[64], acc[64];
    const float* qp = Q + ((size_t)(b * SS + qs)) * HD + h * DD;
    #pragma unroll
    for (int d4 = 0; d4 < 16; d4++) {
        float4 t = ((const float4*)qp)[d4];
        qr[4*d4+0] = t.x * scale; qr[4*d4+1] = t.y * scale;
        qr[4*d4+2] = t.z * scale; qr[4*d4+3] = t.w * scale;
    }
    #pragma unroll
    for (int d = 0; d < 64; d++) acc[d] = 0.f;
    float m = -INFINITY, l = 0.f;

    const float* kbase = Kg + ((size_t)b * SS) * HD + h * DD;
    const float* vbase = Vg + ((size_t)b * SS) * HD + h * DD;

    for (int kt = 0; kt < SS; kt += 64) {
        __syncthreads();
        #pragma unroll
        for (int i = 0; i < 8; i++) {
            int idx = i * 128 + threadIdx.x;
            int r = idx >> 4, c4 = idx & 15;
            ((float4*)Ks[r])[c4] = ((const float4*)(kbase + (size_t)(kt + r) * HD))[c4];
            ((float4*)Vs[r])[c4] = ((const float4*)(vbase + (size_t)(kt + r) * HD))[c4];
        }
        __syncthreads();

        #pragma unroll 1
        for (int c = 0; c < 4; c++) {
            float sc[16];
            float mt = m;
            #pragma unroll
            for (int j = 0; j < 16; j++) {
                const float4* kr = (const float4*)Ks[c * 16 + j];
                float s = 0.f;
                #pragma unroll
                for (int d4 = 0; d4 < 16; d4++) {
                    float4 kk = kr[d4];
                    s = fmaf(qr[4*d4+0], kk.x, s);
                    s = fmaf(qr[4*d4+1], kk.y, s);
                    s = fmaf(qr[4*d4+2], kk.z, s);
                    s = fmaf(qr[4*d4+3], kk.w, s);
                }
                sc[j] = s;
                mt = fmaxf(mt, s);
            }
            const float corr = __expf(m - mt);
            l *= corr;
            #pragma unroll
            for (int d = 0; d < 64; d++) acc[d] *= corr;
            #pragma unroll
            for (int j = 0; j < 16; j++) {
                float p = __expf(sc[j] - mt);
                l += p;
                const float4* vr = (const float4*)Vs[c * 16 + j];
                #pragma unroll
                for (int d4 = 0; d4 < 16; d4++) {
                    float4 vv = vr[d4];
                    acc[4*d4+0] = fmaf(p, vv.x, acc[4*d4+0]);
                    acc[4*d4+1] = fmaf(p, vv.y, acc[4*d4+1]);
                    acc[4*d4+2] = fmaf(p, vv.z, acc[4*d4+2]);
                    acc[4*d4+3] = fmaf(p, vv.w, acc[4*d4+3]);
                }
            }
            m = mt;
        }
    }

    const float invl = 1.f / l;
    float4* op = (float4*)(O + ((size_t)(b * SS + qs)) * HD + h * DD);
    #pragma unroll
    for (int d4 = 0; d4 < 16; d4++)
        op[d4] = make_float4(acc[4*d4+0]*invl, acc[4*d4+1]*invl,
                             acc[4*d4+2]*invl, acc[4*d4+3]*invl);
}

// ---------------- LayerNorm over last dim (1024), eps=1e-12 ----------------
__global__ __launch_bounds__(256)
void ln_kernel(const float* __restrict__ in, const float* __restrict__ gamma,
               const float* __restrict__ beta, float* __restrict__ out)
{
    const int row = blockIdx.x;
    const int tid = threadIdx.x;
    const float4 xv = ((const float4*)(in + (size_t)row * HD))[tid];

    __shared__ float red[32];
    float s = xv.x + xv.y + xv.z + xv.w;
    #pragma unroll
    for (int o = 16; o > 0; o >>= 1) s += __shfl_xor_sync(0xffffffffu, s, o);
    if ((tid & 31) == 0) red[tid >> 5] = s;
    __syncthreads();
    if (tid < 32) {
        float t = (tid < 8) ? red[tid] : 0.f;
        #pragma unroll
        for (int o = 4; o > 0; o >>= 1) t += __shfl_xor_sync(0xffffffffu, t, o);
        if (tid == 0) red[0] = t;
    }
    __syncthreads();
    const float mu = red[0] * (1.f / 1024.f);
    __syncthreads();   // everyone done reading red[0]

    const float dx = xv.x - mu, dy = xv.y - mu, dz = xv.z - mu, dw = xv.w - mu;
    float sq = dx*dx + dy*dy + dz*dz + dw*dw;
    #pragma unroll
    for (int o = 16; o > 0; o >>= 1) sq += __shfl_xor_sync(0xffffffffu, sq, o);
    if ((tid & 31) == 0) red[tid >> 5] = sq;
    __syncthreads();
    if (tid < 32) {
        float t = (tid < 8) ? red[tid] : 0.f;
        #pragma unroll
        for (int o = 4; o > 0; o >>= 1) t += __shfl_xor_sync(0xffffffffu, t, o);
        if (tid == 0) red[0] = t;
    }
    __syncthreads();
    const float var  = red[0] * (1.f / 1024.f);
    const float rstd = rsqrtf(var + 1e-12f);

    const float4 gv = ((const float4*)gamma)[tid];
    const float4 bv = ((const float4*)beta )[tid];
    float4 ov;
    ov.x = dx * rstd * gv.x + bv.x;
    ov.y = dy * rstd * gv.y + bv.y;
    ov.z = dz * rstd * gv.z + bv.z;
    ov.w = dw * rstd * gv.w + bv.w;
    ((float4*)(out + (size_t)row * HD))[tid] = ov;
}

// ---------------- launch ----------------------------------------------------
extern "C" void kernel_launch(void* const* d_in, const int* in_sizes, int n_in,
                              void* d_out, int out_size)
{
    const float* x     = (const float*)d_in[0];
    const float* Wq    = (const float*)d_in[1];
    const float* bq    = (const float*)d_in[2];
    const float* Wk    = (const float*)d_in[3];
    const float* bk    = (const float*)d_in[4];
    const float* Wv    = (const float*)d_in[5];
    const float* bv    = (const float*)d_in[6];
    const float* Wo    = (const float*)d_in[7];
    const float* bo    = (const float*)d_in[8];
    const float* g1    = (const float*)d_in[9];
    const float* beta1 = (const float*)d_in[10];
    const float* W1    = (const float*)d_in[11];
    const float* b1    = (const float*)d_in[12];
    const float* W2    = (const float*)d_in[13];
    const float* b2    = (const float*)d_in[14];
    const float* g2    = (const float*)d_in[15];
    const float* beta2 = (const float*)d_in[16];
    float* out = (float*)d_out;

    float *q, *k, *v, *ctx, *r1, *h, *ff, *r2;
    cudaGetSymbolAddress((void**)&q,   g_q);
    cudaGetSymbolAddress((void**)&k,   g_k);
    cudaGetSymbolAddress((void**)&v,   g_v);
    cudaGetSymbolAddress((void**)&ctx, g_ctx);
    cudaGetSymbolAddress((void**)&r1,  g_r1);
    cudaGetSymbolAddress((void**)&h,   g_h);
    cudaGetSymbolAddress((void**)&ff,  g_ff);
    cudaGetSymbolAddress((void**)&r2,  g_r2);

    const dim3 gHd (HD  / 128, BSR / 128);   // (8, 64)
    const dim3 gFf (FFD / 128, BSR / 128);   // (32, 64)

    // QKV projections
    gemm_kernel<0><<<gHd, 256>>>(x, Wq, bq, nullptr, q, BSR, HD, HD);
    gemm_kernel<0><<<gHd, 256>>>(x, Wk, bk, nullptr, k, BSR, HD, HD);
    gemm_kernel<0><<<gHd, 256>>>(x, Wv, bv, nullptr, v, BSR, HD, HD);

    // RoPE on q,k
    rope_kernel<<<(BSR * (HD / 2)) / 256, 256>>>(q, k);

    // Flash attention -> ctx
    attn_kernel<<<dim3(SS / 128, BB * NHH), 128>>>(q, k, v, ctx);

    // O projection + residual(x) -> r1 ; LN -> h
    gemm_kernel<0><<<gHd, 256>>>(ctx, Wo, bo, x, r1, BSR, HD, HD);
    ln_kernel<<<BSR, 256>>>(r1, g1, beta1, h);

    // FFN
    gemm_kernel<1><<<gFf, 256>>>(h,  W1, b1, nullptr, ff, BSR, FFD, HD);
    gemm_kernel<0><<<gHd, 256>>>(ff, W2, b2, h,       r2, BSR, HD, FFD);

    // final LN -> out
    ln_kernel<<<BSR, 256>>>(r2, g2, beta2, out);
}

// round 4
// speedup vs baseline: 1.7322x; 1.7322x over previous
#include <cuda_runtime.h>
#include <cuda_bf16.h>
#include <math.h>
#include <stdint.h>

// Problem constants
#define BB   4
#define SS   2048
#define HD   1024
#define NHH  16
#define DD   64
#define FFD  4096
#define BSR  (BB*SS)          // 8192 rows

// ---------------- scratch (device globals: no allocation allowed) ----------
__device__ float g_q  [BSR * HD];
__device__ float g_k  [BSR * HD];
__device__ float g_v  [BSR * HD];
__device__ float g_ctx[BSR * HD];
__device__ float g_r1 [BSR * HD];
__device__ float g_h  [BSR * HD];
__device__ float g_ff [BSR * FFD];
__device__ float g_r2 [BSR * HD];
// transposed (N,K) tf32-rounded weights
__device__ float g_wqt[HD * HD];
__device__ float g_wkt[HD * HD];
__device__ float g_wvt[HD * HD];
__device__ float g_wot[HD * HD];
__device__ float g_w1t[FFD * HD];
__device__ float g_w2t[HD * FFD];
// rope inverse-frequency table
__device__ float g_ropeinv[32];

__device__ __forceinline__ float tf32r(float x) {
    float r;
    asm("cvt.rna.tf32.f32 %0, %1;" : "=f"(r) : "f"(x));
    return r;
}

// =================== tf32 mma.sync GEMM ====================================
// C[M,N] = A[M,K] @ Bt[N,K]^T (+bias, +add, optional gelu)
// BM=BN=128, BK=16, 256 threads (8 warps), warp tile 64x32.
#define SMS 20   // smem row stride in floats (16 + 4 pad)

__device__ __forceinline__ void mma_tf32_16x8x8(float* c, const uint32_t* a, const uint32_t* b) {
    asm volatile(
        "mma.sync.aligned.m16n8k8.row.col.f32.tf32.tf32.f32 "
        "{%0,%1,%2,%3}, {%4,%5,%6,%7}, {%8,%9}, {%0,%1,%2,%3};"
        : "+f"(c[0]), "+f"(c[1]), "+f"(c[2]), "+f"(c[3])
        : "r"(a[0]), "r"(a[1]), "r"(a[2]), "r"(a[3]), "r"(b[0]), "r"(b[1]));
}

template<int EPI>   // 0 = none, 1 = gelu(tanh)
__global__ __launch_bounds__(256)
void gemm_mma(const float* __restrict__ A, const float* __restrict__ Bt,
              const float* __restrict__ bias, const float* __restrict__ add,
              float* __restrict__ C, int M, int N, int K)
{
    __shared__ float As[2][128 * SMS];
    __shared__ float Bs[2][128 * SMS];

    const int tid  = threadIdx.x;
    const int wid  = tid >> 5;
    const int lane = tid & 31;
    const int g    = lane >> 2;       // 0..7
    const int t    = lane & 3;        // 0..3

    const int crow = blockIdx.y * 128;
    const int ccol = blockIdx.x * 128;

    const int wm = wid & 1;           // 2 row groups of 64
    const int wn = wid >> 1;          // 4 col groups of 32
    const int rb = wm * 64;
    const int cb = wn * 32;

    // global-load assignment: each thread 2 float4 per tile (A and B alike)
    const int ldrow = tid >> 1;               // 0..127
    const int ldc0  = (tid & 1) * 8;          // 0 or 8
    const float* Ap = A  + (size_t)(crow + ldrow) * K + ldc0;
    const float* Bp = Bt + (size_t)(ccol + ldrow) * K + ldc0;

    float acc[4][4][4];
    #pragma unroll
    for (int i = 0; i < 4; i++)
        #pragma unroll
        for (int j = 0; j < 4; j++)
            #pragma unroll
            for (int e = 0; e < 4; e++) acc[i][j][e] = 0.f;

    const int niter = K >> 4;

    // prologue: tile 0 -> smem
    float4 pa0 = *(const float4*)(Ap + 0);
    float4 pa1 = *(const float4*)(Ap + 4);
    float4 pb0 = *(const float4*)(Bp + 0);
    float4 pb1 = *(const float4*)(Bp + 4);
    {
        float* as = &As[0][ldrow * SMS + ldc0];
        float* bs = &Bs[0][ldrow * SMS + ldc0];
        as[0]=tf32r(pa0.x); as[1]=tf32r(pa0.y); as[2]=tf32r(pa0.z); as[3]=tf32r(pa0.w);
        as[4]=tf32r(pa1.x); as[5]=tf32r(pa1.y); as[6]=tf32r(pa1.z); as[7]=tf32r(pa1.w);
        bs[0]=tf32r(pb0.x); bs[1]=tf32r(pb0.y); bs[2]=tf32r(pb0.z); bs[3]=tf32r(pb0.w);
        bs[4]=tf32r(pb1.x); bs[5]=tf32r(pb1.y); bs[6]=tf32r(pb1.z); bs[7]=tf32r(pb1.w);
    }
    __syncthreads();

    for (int it = 0; it < niter; ++it) {
        const int cur = it & 1;
        // prefetch next tile into registers
        if (it + 1 < niter) {
            const int k0 = (it + 1) << 4;
            pa0 = *(const float4*)(Ap + k0 + 0);
            pa1 = *(const float4*)(Ap + k0 + 4);
            pb0 = *(const float4*)(Bp + k0 + 0);
            pb1 = *(const float4*)(Bp + k0 + 4);
        }

        const float* as = &As[cur][0];
        const float* bs = &Bs[cur][0];
        #pragma unroll
        for (int kk = 0; kk < 16; kk += 8) {
            uint32_t af[4][4], bf[4][2];
            #pragma unroll
            for (int mt = 0; mt < 4; mt++) {
                const int base = (rb + mt * 16 + g) * SMS + kk + t;
                af[mt][0] = __float_as_uint(as[base]);
                af[mt][1] = __float_as_uint(as[base + 8 * SMS]);
                af[mt][2] = __float_as_uint(as[base + 4]);
                af[mt][3] = __float_as_uint(as[base + 8 * SMS + 4]);
            }
            #pragma unroll
            for (int nt = 0; nt < 4; nt++) {
                const int base = (cb + nt * 8 + g) * SMS + kk + t;
                bf[nt][0] = __float_as_uint(bs[base]);
                bf[nt][1] = __float_as_uint(bs[base + 4]);
            }
            #pragma unroll
            for (int mt = 0; mt < 4; mt++)
                #pragma unroll
                for (int nt = 0; nt < 4; nt++)
                    mma_tf32_16x8x8(acc[mt][nt], af[mt], bf[nt]);
        }

        if (it + 1 < niter) {
            __syncthreads();     // everyone done reading buf cur^1 (2 iters ago)
            float* asn = &As[cur ^ 1][ldrow * SMS + ldc0];
            float* bsn = &Bs[cur ^ 1][ldrow * SMS + ldc0];
            asn[0]=tf32r(pa0.x); asn[1]=tf32r(pa0.y); asn[2]=tf32r(pa0.z); asn[3]=tf32r(pa0.w);
            asn[4]=tf32r(pa1.x); asn[5]=tf32r(pa1.y); asn[6]=tf32r(pa1.z); asn[7]=tf32r(pa1.w);
            bsn[0]=tf32r(pb0.x); bsn[1]=tf32r(pb0.y); bsn[2]=tf32r(pb0.z); bsn[3]=tf32r(pb0.w);
            bsn[4]=tf32r(pb1.x); bsn[5]=tf32r(pb1.y); bsn[6]=tf32r(pb1.z); bsn[7]=tf32r(pb1.w);
            __syncthreads();
        }
    }

    // epilogue
    #pragma unroll
    for (int mt = 0; mt < 4; mt++) {
        #pragma unroll
        for (int half = 0; half < 2; half++) {
            const int r = crow + rb + mt * 16 + g + half * 8;
            #pragma unroll
            for (int nt = 0; nt < 4; nt++) {
                const int c0 = ccol + cb + nt * 8 + t * 2;
                float v0 = acc[mt][nt][half * 2 + 0] + bias[c0 + 0];
                float v1 = acc[mt][nt][half * 2 + 1] + bias[c0 + 1];
                if (add) {
                    const float2 a2 = *(const float2*)(add + (size_t)r * N + c0);
                    v0 += a2.x; v1 += a2.y;
                }
                if (EPI == 1) {
                    v0 = 0.5f * v0 * (1.f + tanhf(0.7978845608028654f * (v0 + 0.044715f * v0 * v0 * v0)));
                    v1 = 0.5f * v1 * (1.f + tanhf(0.7978845608028654f * (v1 + 0.044715f * v1 * v1 * v1)));
                }
                *(float2*)(C + (size_t)r * N + c0) = make_float2(v0, v1);
            }
        }
    }
}

// ------------- weight transpose + tf32 rounding: in[R,C] -> out[C,R] -------
__global__ __launch_bounds__(256)
void transpose_rna(const float* __restrict__ in, float* __restrict__ out, int R, int C)
{
    __shared__ float t[32][33];
    const int bx = blockIdx.x * 32, by = blockIdx.y * 32;
    const int tx = threadIdx.x, ty = threadIdx.y;
    #pragma unroll
    for (int i = 0; i < 32; i += 8)
        t[ty + i][tx] = in[(size_t)(by + ty + i) * C + bx + tx];
    __syncthreads();
    #pragma unroll
    for (int i = 0; i < 32; i += 8)
        out[(size_t)(bx + ty + i) * R + by + tx] = tf32r(t[tx][ty + i]);
}

// ---------------- RoPE -----------------------------------------------------
__global__ void rope_tab_kernel() {
    const int i = threadIdx.x;
    if (i < 32) g_ropeinv[i] = (float)pow(10000.0, -((double)(2 * i)) / 64.0);
}
__global__ __launch_bounds__(256)
void rope_kernel(float* __restrict__ q, float* __restrict__ k)
{
    const int idx = blockIdx.x * blockDim.x + threadIdx.x;   // one pair
    if (idx >= BSR * (HD / 2)) return;
    const int row = idx >> 9;
    const int p   = idx & 511;
    const int s   = row & (SS - 1);
    const int i   = p & 31;

    const float ang = (float)s * g_ropeinv[i];
    float sn, c;
    sincosf(ang, &sn, &c);

    float2* qp = (float2*)(q + (size_t)row * HD) + p;
    float2* kp = (float2*)(k + (size_t)row * HD) + p;
    const float2 qv = *qp, kv = *kp;
    float2 qo, ko;
    qo.x = qv.x * c - qv.y * sn;  qo.y = qv.y * c + qv.x * sn;
    ko.x = kv.x * c - kv.y * sn;  ko.y = kv.y * c + kv.x * sn;
    *qp = qo; *kp = ko;
}

// ---------------- Flash attention (SIMT, fp32) -----------------------------
__global__ __launch_bounds__(128)
void attn_kernel(const float* __restrict__ Q, const float* __restrict__ Kg,
                 const float* __restrict__ Vg, float* __restrict__ O)
{
    __shared__ float Ks[64][64];
    __shared__ float Vs[64][64];

    const int bh = blockIdx.y;
    const int b  = bh >> 4;
    const int h  = bh & 15;
    const int qs = blockIdx.x * 128 + threadIdx.x;
    const float scale = 0.125f;

    float qr[64], acc[64];
    const float* qp = Q + ((size_t)(b * SS + qs)) * HD + h * DD;
    #pragma unroll
    for (int d4 = 0; d4 < 16; d4++) {
        float4 t = ((const float4*)qp)[d4];
        qr[4*d4+0] = t.x * scale; qr[4*d4+1] = t.y * scale;
        qr[4*d4+2] = t.z * scale; qr[4*d4+3] = t.w * scale;
    }
    #pragma unroll
    for (int d = 0; d < 64; d++) acc[d] = 0.f;
    float m = -INFINITY, l = 0.f;

    const float* kbase = Kg + ((size_t)b * SS) * HD + h * DD;
    const float* vbase = Vg + ((size_t)b * SS) * HD + h * DD;

    for (int kt = 0; kt < SS; kt += 64) {
        __syncthreads();
        #pragma unroll
        for (int i = 0; i < 8; i++) {
            int idx = i * 128 + threadIdx.x;
            int r = idx >> 4, c4 = idx & 15;
            ((float4*)Ks[r])[c4] = ((const float4*)(kbase + (size_t)(kt + r) * HD))[c4];
            ((float4*)Vs[r])[c4] = ((const float4*)(vbase + (size_t)(kt + r) * HD))[c4];
        }
        __syncthreads();

        #pragma unroll 1
        for (int c = 0; c < 4; c++) {
            float sc[16];
            float mt = m;
            #pragma unroll
            for (int j = 0; j < 16; j++) {
                const float4* kr = (const float4*)Ks[c * 16 + j];
                float s = 0.f;
                #pragma unroll
                for (int d4 = 0; d4 < 16; d4++) {
                    float4 kk = kr[d4];
                    s = fmaf(qr[4*d4+0], kk.x, s);
                    s = fmaf(qr[4*d4+1], kk.y, s);
                    s = fmaf(qr[4*d4+2], kk.z, s);
                    s = fmaf(qr[4*d4+3], kk.w, s);
                }
                sc[j] = s;
                mt = fmaxf(mt, s);
            }
            const float corr = __expf(m - mt);
            l *= corr;
            #pragma unroll
            for (int d = 0; d < 64; d++) acc[d] *= corr;
            #pragma unroll
            for (int j = 0; j < 16; j++) {
                float p = __expf(sc[j] - mt);
                l += p;
                const float4* vr = (const float4*)Vs[c * 16 + j];
                #pragma unroll
                for (int d4 = 0; d4 < 16; d4++) {
                    float4 vv = vr[d4];
                    acc[4*d4+0] = fmaf(p, vv.x, acc[4*d4+0]);
                    acc[4*d4+1] = fmaf(p, vv.y, acc[4*d4+1]);
                    acc[4*d4+2] = fmaf(p, vv.z, acc[4*d4+2]);
                    acc[4*d4+3] = fmaf(p, vv.w, acc[4*d4+3]);
                }
            }
            m = mt;
        }
    }

    const float invl = 1.f / l;
    float4* op = (float4*)(O + ((size_t)(b * SS + qs)) * HD + h * DD);
    #pragma unroll
    for (int d4 = 0; d4 < 16; d4++)
        op[d4] = make_float4(acc[4*d4+0]*invl, acc[4*d4+1]*invl,
                             acc[4*d4+2]*invl, acc[4*d4+3]*invl);
}

// ---------------- LayerNorm over last dim (1024), eps=1e-12 ----------------
__global__ __launch_bounds__(256)
void ln_kernel(const float* __restrict__ in, const float* __restrict__ gamma,
               const float* __restrict__ beta, float* __restrict__ out)
{
    const int row = blockIdx.x;
    const int tid = threadIdx.x;
    const float4 xv = ((const float4*)(in + (size_t)row * HD))[tid];

    __shared__ float red[32];
    float s = xv.x + xv.y + xv.z + xv.w;
    #pragma unroll
    for (int o = 16; o > 0; o >>= 1) s += __shfl_xor_sync(0xffffffffu, s, o);
    if ((tid & 31) == 0) red[tid >> 5] = s;
    __syncthreads();
    if (tid < 32) {
        float t = (tid < 8) ? red[tid] : 0.f;
        #pragma unroll
        for (int o = 4; o > 0; o >>= 1) t += __shfl_xor_sync(0xffffffffu, t, o);
        if (tid == 0) red[0] = t;
    }
    __syncthreads();
    const float mu = red[0] * (1.f / 1024.f);
    __syncthreads();

    const float dx = xv.x - mu, dy = xv.y - mu, dz = xv.z - mu, dw = xv.w - mu;
    float sq = dx*dx + dy*dy + dz*dz + dw*dw;
    #pragma unroll
    for (int o = 16; o > 0; o >>= 1) sq += __shfl_xor_sync(0xffffffffu, sq, o);
    if ((tid & 31) == 0) red[tid >> 5] = sq;
    __syncthreads();
    if (tid < 32) {
        float t = (tid < 8) ? red[tid] : 0.f;
        #pragma unroll
        for (int o = 4; o > 0; o >>= 1) t += __shfl_xor_sync(0xffffffffu, t, o);
        if (tid == 0) red[0] = t;
    }
    __syncthreads();
    const float var  = red[0] * (1.f / 1024.f);
    const float rstd = rsqrtf(var + 1e-12f);

    const float4 gv = ((const float4*)gamma)[tid];
    const float4 bv = ((const float4*)beta )[tid];
    float4 ov;
    ov.x = dx * rstd * gv.x + bv.x;
    ov.y = dy * rstd * gv.y + bv.y;
    ov.z = dz * rstd * gv.z + bv.z;
    ov.w = dw * rstd * gv.w + bv.w;
    ((float4*)(out + (size_t)row * HD))[tid] = ov;
}

// ---------------- launch ----------------------------------------------------
extern "C" void kernel_launch(void* const* d_in, const int* in_sizes, int n_in,
                              void* d_out, int out_size)
{
    const float* x     = (const float*)d_in[0];
    const float* Wq    = (const float*)d_in[1];
    const float* bq    = (const float*)d_in[2];
    const float* Wk    = (const float*)d_in[3];
    const float* bk    = (const float*)d_in[4];
    const float* Wv    = (const float*)d_in[5];
    const float* bv    = (const float*)d_in[6];
    const float* Wo    = (const float*)d_in[7];
    const float* bo    = (const float*)d_in[8];
    const float* g1    = (const float*)d_in[9];
    const float* beta1 = (const float*)d_in[10];
    const float* W1    = (const float*)d_in[11];
    const float* b1    = (const float*)d_in[12];
    const float* W2    = (const float*)d_in[13];
    const float* b2    = (const float*)d_in[14];
    const float* g2    = (const float*)d_in[15];
    const float* beta2 = (const float*)d_in[16];
    float* out = (float*)d_out;

    float *q, *k, *v, *ctx, *r1, *h, *ff, *r2;
    float *wqt, *wkt, *wvt, *wot, *w1t, *w2t;
    cudaGetSymbolAddress((void**)&q,   g_q);
    cudaGetSymbolAddress((void**)&k,   g_k);
    cudaGetSymbolAddress((void**)&v,   g_v);
    cudaGetSymbolAddress((void**)&ctx, g_ctx);
    cudaGetSymbolAddress((void**)&r1,  g_r1);
    cudaGetSymbolAddress((void**)&h,   g_h);
    cudaGetSymbolAddress((void**)&ff,  g_ff);
    cudaGetSymbolAddress((void**)&r2,  g_r2);
    cudaGetSymbolAddress((void**)&wqt, g_wqt);
    cudaGetSymbolAddress((void**)&wkt, g_wkt);
    cudaGetSymbolAddress((void**)&wvt, g_wvt);
    cudaGetSymbolAddress((void**)&wot, g_wot);
    cudaGetSymbolAddress((void**)&w1t, g_w1t);
    cudaGetSymbolAddress((void**)&w2t, g_w2t);

    // rope table + weight transposes (tf32-rounded, [N,K] layout)
    rope_tab_kernel<<<1, 32>>>();
    const dim3 tb(32, 8);
    transpose_rna<<<dim3(HD / 32,  HD / 32),  tb>>>(Wq, wqt, HD,  HD);
    transpose_rna<<<dim3(HD / 32,  HD / 32),  tb>>>(Wk, wkt, HD,  HD);
    transpose_rna<<<dim3(HD / 32,  HD / 32),  tb>>>(Wv, wvt, HD,  HD);
    transpose_rna<<<dim3(HD / 32,  HD / 32),  tb>>>(Wo, wot, HD,  HD);
    transpose_rna<<<dim3(FFD / 32, HD / 32),  tb>>>(W1, w1t, HD,  FFD);
    transpose_rna<<<dim3(HD / 32,  FFD / 32), tb>>>(W2, w2t, FFD, HD);

    const dim3 gHd(HD  / 128, BSR / 128);   // (8, 64)
    const dim3 gFf(FFD / 128, BSR / 128);   // (32, 64)

    // QKV projections (tf32 mma.sync)
    gemm_mma<0><<<gHd, 256>>>(x, wqt, bq, nullptr, q, BSR, HD, HD);
    gemm_mma<0><<<gHd, 256>>>(x, wkt, bk, nullptr, k, BSR, HD, HD);
    gemm_mma<0><<<gHd, 256>>>(x, wvt, bv, nullptr, v, BSR, HD, HD);

    // RoPE
    rope_kernel<<<(BSR * (HD / 2)) / 256, 256>>>(q, k);

    // Flash attention -> ctx
    attn_kernel<<<dim3(SS / 128, BB * NHH), 128>>>(q, k, v, ctx);

    // O projection + residual(x) -> r1 ; LN -> h
    gemm_mma<0><<<gHd, 256>>>(ctx, wot, bo, x, r1, BSR, HD, HD);
    ln_kernel<<<BSR, 256>>>(r1, g1, beta1, h);

    // FFN
    gemm_mma<1><<<gFf, 256>>>(h,  w1t, b1, nullptr, ff, BSR, FFD, HD);
    gemm_mma<0><<<gHd, 256>>>(ff, w2t, b2, h,       r2, BSR, HD, FFD);

    // final LN -> out
    ln_kernel<<<BSR, 256>>>(r2, g2, beta2, out);
}

// round 5
// speedup vs baseline: 2.8240x; 1.6303x over previous
#include <cuda_runtime.h>
#include <cuda_bf16.h>
#include <math.h>
#include <stdint.h>

// Problem constants
#define BB   4
#define SS   2048
#define HD   1024
#define NHH  16
#define DD   64
#define FFD  4096
#define BSR  (BB*SS)          // 8192 rows
#define LOG2E 1.4426950408889634f

// ---------------- scratch (device globals: no allocation allowed) ----------
__device__ float g_q  [BSR * HD];
__device__ float g_k  [BSR * HD];
__device__ float g_v  [BSR * HD];
__device__ float g_ctx[BSR * HD];
__device__ float g_r1 [BSR * HD];
__device__ float g_h  [BSR * HD];
__device__ float g_ff [BSR * FFD];
__device__ float g_r2 [BSR * HD];
// transposed (N,K) tf32-rounded weights
__device__ float g_wqt[HD * HD];
__device__ float g_wkt[HD * HD];
__device__ float g_wvt[HD * HD];
__device__ float g_wot[HD * HD];
__device__ float g_w1t[FFD * HD];
__device__ float g_w2t[HD * FFD];
// rope inverse-frequency table
__device__ float g_ropeinv[32];

__device__ __forceinline__ float tf32r(float x) {
    float r;
    asm("cvt.rna.tf32.f32 %0, %1;" : "=f"(r) : "f"(x));
    return r;
}

// fast exp2 on the fma/alu pipes (valid for x <= ~0; clamps at -126)
__device__ __forceinline__ float fexp2(float x) {
    x = fmaxf(x, -126.f);
    const float k = x + 12582912.f;              // 1.5*2^23: rint via magic
    const int   ik = __float_as_int(k) - 0x4B400000;
    const float f = x - (k - 12582912.f);        // f in [-0.5, 0.5]
    float p = 9.6181291e-3f;                     // Taylor of 2^f
    p = fmaf(p, f, 5.5504109e-2f);
    p = fmaf(p, f, 2.4022651e-1f);
    p = fmaf(p, f, 6.9314718e-1f);
    p = fmaf(p, f, 1.0f);
    return __int_as_float(__float_as_int(p) + (ik << 23));
}

__device__ __forceinline__ void mma_tf32_16x8x8(float* c, const uint32_t* a, const uint32_t* b) {
    asm volatile(
        "mma.sync.aligned.m16n8k8.row.col.f32.tf32.tf32.f32 "
        "{%0,%1,%2,%3}, {%4,%5,%6,%7}, {%8,%9}, {%0,%1,%2,%3};"
        : "+f"(c[0]), "+f"(c[1]), "+f"(c[2]), "+f"(c[3])
        : "r"(a[0]), "r"(a[1]), "r"(a[2]), "r"(a[3]), "r"(b[0]), "r"(b[1]));
}

// =================== tf32 mma.sync GEMM ====================================
// C[M,N] = A[M,K] @ Bt[N,K]^T (+bias, +add, optional gelu)
// BM=BN=128, BK=16, 256 threads (8 warps), warp tile 64x32.
#define SMS 20   // smem row stride in floats (16 + 4 pad)

template<int EPI>   // 0 = none, 1 = gelu(tanh)
__global__ __launch_bounds__(256)
void gemm_mma(const float* __restrict__ A, const float* __restrict__ Bt,
              const float* __restrict__ bias, const float* __restrict__ add,
              float* __restrict__ C, int M, int N, int K)
{
    __shared__ float As[2][128 * SMS];
    __shared__ float Bs[2][128 * SMS];

    const int tid  = threadIdx.x;
    const int wid  = tid >> 5;
    const int lane = tid & 31;
    const int g    = lane >> 2;       // 0..7
    const int t    = lane & 3;        // 0..3

    const int crow = blockIdx.y * 128;
    const int ccol = blockIdx.x * 128;

    const int wm = wid & 1;           // 2 row groups of 64
    const int wn = wid >> 1;          // 4 col groups of 32
    const int rb = wm * 64;
    const int cb = wn * 32;

    const int ldrow = tid >> 1;               // 0..127
    const int ldc0  = (tid & 1) * 8;          // 0 or 8
    const float* Ap = A  + (size_t)(crow + ldrow) * K + ldc0;
    const float* Bp = Bt + (size_t)(ccol + ldrow) * K + ldc0;

    float acc[4][4][4];
    #pragma unroll
    for (int i = 0; i < 4; i++)
        #pragma unroll
        for (int j = 0; j < 4; j++)
            #pragma unroll
            for (int e = 0; e < 4; e++) acc[i][j][e] = 0.f;

    const int niter = K >> 4;

    float4 pa0 = *(const float4*)(Ap + 0);
    float4 pa1 = *(const float4*)(Ap + 4);
    float4 pb0 = *(const float4*)(Bp + 0);
    float4 pb1 = *(const float4*)(Bp + 4);
    {
        float* as = &As[0][ldrow * SMS + ldc0];
        float* bs = &Bs[0][ldrow * SMS + ldc0];
        as[0]=tf32r(pa0.x); as[1]=tf32r(pa0.y); as[2]=tf32r(pa0.z); as[3]=tf32r(pa0.w);
        as[4]=tf32r(pa1.x); as[5]=tf32r(pa1.y); as[6]=tf32r(pa1.z); as[7]=tf32r(pa1.w);
        bs[0]=tf32r(pb0.x); bs[1]=tf32r(pb0.y); bs[2]=tf32r(pb0.z); bs[3]=tf32r(pb0.w);
        bs[4]=tf32r(pb1.x); bs[5]=tf32r(pb1.y); bs[6]=tf32r(pb1.z); bs[7]=tf32r(pb1.w);
    }
    __syncthreads();

    for (int it = 0; it < niter; ++it) {
        const int cur = it & 1;
        if (it + 1 < niter) {
            const int k0 = (it + 1) << 4;
            pa0 = *(const float4*)(Ap + k0 + 0);
            pa1 = *(const float4*)(Ap + k0 + 4);
            pb0 = *(const float4*)(Bp + k0 + 0);
            pb1 = *(const float4*)(Bp + k0 + 4);
        }

        const float* as = &As[cur][0];
        const float* bs = &Bs[cur][0];
        #pragma unroll
        for (int kk = 0; kk < 16; kk += 8) {
            uint32_t af[4][4], bf[4][2];
            #pragma unroll
            for (int mt = 0; mt < 4; mt++) {
                const int base = (rb + mt * 16 + g) * SMS + kk + t;
                af[mt][0] = __float_as_uint(as[base]);
                af[mt][1] = __float_as_uint(as[base + 8 * SMS]);
                af[mt][2] = __float_as_uint(as[base + 4]);
                af[mt][3] = __float_as_uint(as[base + 8 * SMS + 4]);
            }
            #pragma unroll
            for (int nt = 0; nt < 4; nt++) {
                const int base = (cb + nt * 8 + g) * SMS + kk + t;
                bf[nt][0] = __float_as_uint(bs[base]);
                bf[nt][1] = __float_as_uint(bs[base + 4]);
            }
            #pragma unroll
            for (int mt = 0; mt < 4; mt++)
                #pragma unroll
                for (int nt = 0; nt < 4; nt++)
                    mma_tf32_16x8x8(acc[mt][nt], af[mt], bf[nt]);
        }

        if (it + 1 < niter) {
            __syncthreads();
            float* asn = &As[cur ^ 1][ldrow * SMS + ldc0];
            float* bsn = &Bs[cur ^ 1][ldrow * SMS + ldc0];
            asn[0]=tf32r(pa0.x); asn[1]=tf32r(pa0.y); asn[2]=tf32r(pa0.z); asn[3]=tf32r(pa0.w);
            asn[4]=tf32r(pa1.x); asn[5]=tf32r(pa1.y); asn[6]=tf32r(pa1.z); asn[7]=tf32r(pa1.w);
            bsn[0]=tf32r(pb0.x); bsn[1]=tf32r(pb0.y); bsn[2]=tf32r(pb0.z); bsn[3]=tf32r(pb0.w);
            bsn[4]=tf32r(pb1.x); bsn[5]=tf32r(pb1.y); bsn[6]=tf32r(pb1.z); bsn[7]=tf32r(pb1.w);
            __syncthreads();
        }
    }

    #pragma unroll
    for (int mt = 0; mt < 4; mt++) {
        #pragma unroll
        for (int half = 0; half < 2; half++) {
            const int r = crow + rb + mt * 16 + g + half * 8;
            #pragma unroll
            for (int nt = 0; nt < 4; nt++) {
                const int c0 = ccol + cb + nt * 8 + t * 2;
                float v0 = acc[mt][nt][half * 2 + 0] + bias[c0 + 0];
                float v1 = acc[mt][nt][half * 2 + 1] + bias[c0 + 1];
                if (add) {
                    const float2 a2 = *(const float2*)(add + (size_t)r * N + c0);
                    v0 += a2.x; v1 += a2.y;
                }
                if (EPI == 1) {
                    v0 = 0.5f * v0 * (1.f + tanhf(0.7978845608028654f * (v0 + 0.044715f * v0 * v0 * v0)));
                    v1 = 0.5f * v1 * (1.f + tanhf(0.7978845608028654f * (v1 + 0.044715f * v1 * v1 * v1)));
                }
                *(float2*)(C + (size_t)r * N + c0) = make_float2(v0, v1);
            }
        }
    }
}

// ------------- weight transpose + tf32 rounding: in[R,C] -> out[C,R] -------
__global__ __launch_bounds__(256)
void transpose_rna(const float* __restrict__ in, float* __restrict__ out, int R, int C)
{
    __shared__ float t[32][33];
    const int bx = blockIdx.x * 32, by = blockIdx.y * 32;
    const int tx = threadIdx.x, ty = threadIdx.y;
    #pragma unroll
    for (int i = 0; i < 32; i += 8)
        t[ty + i][tx] = in[(size_t)(by + ty + i) * C + bx + tx];
    __syncthreads();
    #pragma unroll
    for (int i = 0; i < 32; i += 8)
        out[(size_t)(bx + ty + i) * R + by + tx] = tf32r(t[tx][ty + i]);
}

// ---------------- RoPE -----------------------------------------------------
__global__ void rope_tab_kernel() {
    const int i = threadIdx.x;
    if (i < 32) g_ropeinv[i] = (float)pow(10000.0, -((double)(2 * i)) / 64.0);
}
__global__ __launch_bounds__(256)
void rope_kernel(float* __restrict__ q, float* __restrict__ k)
{
    const int idx = blockIdx.x * blockDim.x + threadIdx.x;   // one pair
    if (idx >= BSR * (HD / 2)) return;
    const int row = idx >> 9;
    const int p   = idx & 511;
    const int s   = row & (SS - 1);
    const int i   = p & 31;

    const float ang = (float)s * g_ropeinv[i];
    float sn, c;
    sincosf(ang, &sn, &c);

    float2* qp = (float2*)(q + (size_t)row * HD) + p;
    float2* kp = (float2*)(k + (size_t)row * HD) + p;
    const float2 qv = *qp, kv = *kp;
    float2 qo, ko;
    qo.x = qv.x * c - qv.y * sn;  qo.y = qv.y * c + qv.x * sn;
    ko.x = kv.x * c - kv.y * sn;  ko.y = kv.y * c + kv.x * sn;
    *qp = qo; *kp = ko;
}

// ============== Flash attention on tensor cores (tf32 mma.sync) ============
// grid (S/128, B*NH), 256 threads (8 warps). Warp w owns q-rows [w*16, w*16+16).
// Smem: Ks[64][68], Vt[64][68], Ps[128][68] (Ps doubles as Q staging).
#define ATS 68
__global__ __launch_bounds__(256)
void attn_mma(const float* __restrict__ Q, const float* __restrict__ Kg,
              const float* __restrict__ Vg, float* __restrict__ O)
{
    extern __shared__ float sm[];
    float* Ks = sm;                   // [64][ATS]
    float* Vt = sm + 64 * ATS;        // [64][ATS]  (transposed V: [d][j])
    float* Ps = sm + 128 * ATS;       // [128][ATS]

    const int tid  = threadIdx.x;
    const int wid  = tid >> 5;
    const int lane = tid & 31;
    const int g    = lane >> 2;      // 0..7
    const int t    = lane & 3;       // 0..3
    const int rb   = wid * 16;

    const int bh = blockIdx.y;
    const int b  = bh >> 4;
    const int h  = bh & 15;
    const int q0 = blockIdx.x * 128;

    const float qscale = 0.125f * LOG2E;  // base-2 softmax domain

    // ---- stage Q tile into Ps (scaled + tf32), then pull A fragments ----
    const float* qbase = Q + ((size_t)(b * SS + q0)) * HD + h * DD;
    #pragma unroll
    for (int l = 0; l < 8; l++) {
        const int idx = l * 256 + tid;
        const int r = idx >> 4, c4 = idx & 15;
        const float4 v4 = *(const float4*)(qbase + (size_t)r * HD + c4 * 4);
        float* d = Ps + r * ATS + c4 * 4;
        d[0] = tf32r(v4.x * qscale); d[1] = tf32r(v4.y * qscale);
        d[2] = tf32r(v4.z * qscale); d[3] = tf32r(v4.w * qscale);
    }
    __syncthreads();

    uint32_t qf[8][4];
    #pragma unroll
    for (int kk = 0; kk < 8; kk++) {
        const int base = (rb + g) * ATS + kk * 8 + t;
        qf[kk][0] = __float_as_uint(Ps[base]);
        qf[kk][1] = __float_as_uint(Ps[base + 8 * ATS]);
        qf[kk][2] = __float_as_uint(Ps[base + 4]);
        qf[kk][3] = __float_as_uint(Ps[base + 8 * ATS + 4]);
    }

    float acc[8][4];
    #pragma unroll
    for (int nt = 0; nt < 8; nt++)
        #pragma unroll
        for (int e = 0; e < 4; e++) acc[nt][e] = 0.f;
    float m0 = -1e30f, m1 = -1e30f, l0 = 0.f, l1 = 0.f;

    const float* kbase = Kg + ((size_t)b * SS) * HD + h * DD;
    const float* vbase = Vg + ((size_t)b * SS) * HD + h * DD;

    for (int kt = 0; kt < SS; kt += 64) {
        __syncthreads();   // prior tile's mma reads of Ks/Vt complete
        #pragma unroll
        for (int l = 0; l < 4; l++) {
            const int idx = l * 256 + tid;
            const int r = idx >> 4, c4 = idx & 15;
            const float4 k4 = *(const float4*)(kbase + (size_t)(kt + r) * HD + c4 * 4);
            float* d = Ks + r * ATS + c4 * 4;
            d[0] = tf32r(k4.x); d[1] = tf32r(k4.y); d[2] = tf32r(k4.z); d[3] = tf32r(k4.w);
            const float4 v4 = *(const float4*)(vbase + (size_t)(kt + r) * HD + c4 * 4);
            Vt[(c4 * 4 + 0) * ATS + r] = tf32r(v4.x);
            Vt[(c4 * 4 + 1) * ATS + r] = tf32r(v4.y);
            Vt[(c4 * 4 + 2) * ATS + r] = tf32r(v4.z);
            Vt[(c4 * 4 + 3) * ATS + r] = tf32r(v4.w);
        }
        __syncthreads();

        // ---- S = Q * K^T  (16 x 64 per warp) ----
        float s[8][4];
        #pragma unroll
        for (int nt = 0; nt < 8; nt++)
            #pragma unroll
            for (int e = 0; e < 4; e++) s[nt][e] = 0.f;
        #pragma unroll
        for (int kk = 0; kk < 8; kk++) {
            uint32_t bf[8][2];
            #pragma unroll
            for (int nt = 0; nt < 8; nt++) {
                const int base = (nt * 8 + g) * ATS + kk * 8 + t;
                bf[nt][0] = __float_as_uint(Ks[base]);
                bf[nt][1] = __float_as_uint(Ks[base + 4]);
            }
            #pragma unroll
            for (int nt = 0; nt < 8; nt++)
                mma_tf32_16x8x8(s[nt], qf[kk], bf[nt]);
        }

        // ---- online softmax (base-2 domain) ----
        float rm0 = s[0][0], rm1 = s[0][2];
        #pragma unroll
        for (int nt = 0; nt < 8; nt++) {
            rm0 = fmaxf(rm0, fmaxf(s[nt][0], s[nt][1]));
            rm1 = fmaxf(rm1, fmaxf(s[nt][2], s[nt][3]));
        }
        rm0 = fmaxf(rm0, __shfl_xor_sync(0xffffffffu, rm0, 1));
        rm0 = fmaxf(rm0, __shfl_xor_sync(0xffffffffu, rm0, 2));
        rm1 = fmaxf(rm1, __shfl_xor_sync(0xffffffffu, rm1, 1));
        rm1 = fmaxf(rm1, __shfl_xor_sync(0xffffffffu, rm1, 2));
        const float mt0 = fmaxf(m0, rm0);
        const float mt1 = fmaxf(m1, rm1);
        if (mt0 > m0) {
            const float c0 = fexp2(m0 - mt0);
            l0 *= c0;
            #pragma unroll
            for (int nt = 0; nt < 8; nt++) { acc[nt][0] *= c0; acc[nt][1] *= c0; }
            m0 = mt0;
        }
        if (mt1 > m1) {
            const float c1 = fexp2(m1 - mt1);
            l1 *= c1;
            #pragma unroll
            for (int nt = 0; nt < 8; nt++) { acc[nt][2] *= c1; acc[nt][3] *= c1; }
            m1 = mt1;
        }

        float ps0 = 0.f, ps1 = 0.f;
        #pragma unroll
        for (int nt = 0; nt < 8; nt++) {
            const float p00 = tf32r(fexp2(s[nt][0] - m0));
            const float p01 = tf32r(fexp2(s[nt][1] - m0));
            const float p10 = tf32r(fexp2(s[nt][2] - m1));
            const float p11 = tf32r(fexp2(s[nt][3] - m1));
            ps0 += p00 + p01;
            ps1 += p10 + p11;
            *(float2*)&Ps[(rb + g) * ATS + nt * 8 + 2 * t]     = make_float2(p00, p01);
            *(float2*)&Ps[(rb + g + 8) * ATS + nt * 8 + 2 * t] = make_float2(p10, p11);
        }
        ps0 += __shfl_xor_sync(0xffffffffu, ps0, 1);
        ps0 += __shfl_xor_sync(0xffffffffu, ps0, 2);
        ps1 += __shfl_xor_sync(0xffffffffu, ps1, 1);
        ps1 += __shfl_xor_sync(0xffffffffu, ps1, 2);
        l0 += ps0;
        l1 += ps1;
        __syncwarp();   // Ps region is per-warp: warp-local ordering suffices

        // ---- acc += P * V  (A = Ps[16 x 64], B = Vt) ----
        #pragma unroll
        for (int kk = 0; kk < 8; kk++) {
            uint32_t af[4];
            const int base = (rb + g) * ATS + kk * 8 + t;
            af[0] = __float_as_uint(Ps[base]);
            af[1] = __float_as_uint(Ps[base + 8 * ATS]);
            af[2] = __float_as_uint(Ps[base + 4]);
            af[3] = __float_as_uint(Ps[base + 8 * ATS + 4]);
            #pragma unroll
            for (int nt = 0; nt < 8; nt++) {
                uint32_t bf[2];
                const int vb = (nt * 8 + g) * ATS + kk * 8 + t;
                bf[0] = __float_as_uint(Vt[vb]);
                bf[1] = __float_as_uint(Vt[vb + 4]);
                mma_tf32_16x8x8(acc[nt], af, bf);
            }
        }
    }

    // ---- epilogue ----
    const float i0 = 1.f / l0;
    const float i1 = 1.f / l1;
    const int r0 = q0 + rb + g;
    const int r1 = r0 + 8;
    float* o0 = O + ((size_t)(b * SS + r0)) * HD + h * DD;
    float* o1 = O + ((size_t)(b * SS + r1)) * HD + h * DD;
    #pragma unroll
    for (int nt = 0; nt < 8; nt++) {
        *(float2*)(o0 + nt * 8 + 2 * t) = make_float2(acc[nt][0] * i0, acc[nt][1] * i0);
        *(float2*)(o1 + nt * 8 + 2 * t) = make_float2(acc[nt][2] * i1, acc[nt][3] * i1);
    }
}

// ---------------- LayerNorm over last dim (1024), eps=1e-12 ----------------
__global__ __launch_bounds__(256)
void ln_kernel(const float* __restrict__ in, const float* __restrict__ gamma,
               const float* __restrict__ beta, float* __restrict__ out)
{
    const int row = blockIdx.x;
    const int tid = threadIdx.x;
    const float4 xv = ((const float4*)(in + (size_t)row * HD))[tid];

    __shared__ float red[32];
    float s = xv.x + xv.y + xv.z + xv.w;
    #pragma unroll
    for (int o = 16; o > 0; o >>= 1) s += __shfl_xor_sync(0xffffffffu, s, o);
    if ((tid & 31) == 0) red[tid >> 5] = s;
    __syncthreads();
    if (tid < 32) {
        float t = (tid < 8) ? red[tid] : 0.f;
        #pragma unroll
        for (int o = 4; o > 0; o >>= 1) t += __shfl_xor_sync(0xffffffffu, t, o);
        if (tid == 0) red[0] = t;
    }
    __syncthreads();
    const float mu = red[0] * (1.f / 1024.f);
    __syncthreads();

    const float dx = xv.x - mu, dy = xv.y - mu, dz = xv.z - mu, dw = xv.w - mu;
    float sq = dx*dx + dy*dy + dz*dz + dw*dw;
    #pragma unroll
    for (int o = 16; o > 0; o >>= 1) sq += __shfl_xor_sync(0xffffffffu, sq, o);
    if ((tid & 31) == 0) red[tid >> 5] = sq;
    __syncthreads();
    if (tid < 32) {
        float t = (tid < 8) ? red[tid] : 0.f;
        #pragma unroll
        for (int o = 4; o > 0; o >>= 1) t += __shfl_xor_sync(0xffffffffu, t, o);
        if (tid == 0) red[0] = t;
    }
    __syncthreads();
    const float var  = red[0] * (1.f / 1024.f);
    const float rstd = rsqrtf(var + 1e-12f);

    const float4 gv = ((const float4*)gamma)[tid];
    const float4 bv = ((const float4*)beta )[tid];
    float4 ov;
    ov.x = dx * rstd * gv.x + bv.x;
    ov.y = dy * rstd * gv.y + bv.y;
    ov.z = dz * rstd * gv.z + bv.z;
    ov.w = dw * rstd * gv.w + bv.w;
    ((float4*)(out + (size_t)row * HD))[tid] = ov;
}

// ---------------- launch ----------------------------------------------------
extern "C" void kernel_launch(void* const* d_in, const int* in_sizes, int n_in,
                              void* d_out, int out_size)
{
    const float* x     = (const float*)d_in[0];
    const float* Wq    = (const float*)d_in[1];
    const float* bq    = (const float*)d_in[2];
    const float* Wk    = (const float*)d_in[3];
    const float* bk    = (const float*)d_in[4];
    const float* Wv    = (const float*)d_in[5];
    const float* bv    = (const float*)d_in[6];
    const float* Wo    = (const float*)d_in[7];
    const float* bo    = (const float*)d_in[8];
    const float* g1    = (const float*)d_in[9];
    const float* beta1 = (const float*)d_in[10];
    const float* W1    = (const float*)d_in[11];
    const float* b1    = (const float*)d_in[12];
    const float* W2    = (const float*)d_in[13];
    const float* b2    = (const float*)d_in[14];
    const float* g2    = (const float*)d_in[15];
    const float* beta2 = (const float*)d_in[16];
    float* out = (float*)d_out;

    float *q, *k, *v, *ctx, *r1, *h, *ff, *r2;
    float *wqt, *wkt, *wvt, *wot, *w1t, *w2t;
    cudaGetSymbolAddress((void**)&q,   g_q);
    cudaGetSymbolAddress((void**)&k,   g_k);
    cudaGetSymbolAddress((void**)&v,   g_v);
    cudaGetSymbolAddress((void**)&ctx, g_ctx);
    cudaGetSymbolAddress((void**)&r1,  g_r1);
    cudaGetSymbolAddress((void**)&h,   g_h);
    cudaGetSymbolAddress((void**)&ff,  g_ff);
    cudaGetSymbolAddress((void**)&r2,  g_r2);
    cudaGetSymbolAddress((void**)&wqt, g_wqt);
    cudaGetSymbolAddress((void**)&wkt, g_wkt);
    cudaGetSymbolAddress((void**)&wvt, g_wvt);
    cudaGetSymbolAddress((void**)&wot, g_wot);
    cudaGetSymbolAddress((void**)&w1t, g_w1t);
    cudaGetSymbolAddress((void**)&w2t, g_w2t);

    const int ATT_SMEM = 256 * ATS * 4;   // 69632 B
    cudaFuncSetAttribute(attn_mma, cudaFuncAttributeMaxDynamicSharedMemorySize, ATT_SMEM);

    // rope table + weight transposes (tf32-rounded, [N,K] layout)
    rope_tab_kernel<<<1, 32>>>();
    const dim3 tb(32, 8);
    transpose_rna<<<dim3(HD / 32,  HD / 32),  tb>>>(Wq, wqt, HD,  HD);
    transpose_rna<<<dim3(HD / 32,  HD / 32),  tb>>>(Wk, wkt, HD,  HD);
    transpose_rna<<<dim3(HD / 32,  HD / 32),  tb>>>(Wv, wvt, HD,  HD);
    transpose_rna<<<dim3(HD / 32,  HD / 32),  tb>>>(Wo, wot, HD,  HD);
    transpose_rna<<<dim3(FFD / 32, HD / 32),  tb>>>(W1, w1t, HD,  FFD);
    transpose_rna<<<dim3(HD / 32,  FFD / 32), tb>>>(W2, w2t, FFD, HD);

    const dim3 gHd(HD  / 128, BSR / 128);   // (8, 64)
    const dim3 gFf(FFD / 128, BSR / 128);   // (32, 64)

    // QKV projections (tf32 mma.sync)
    gemm_mma<0><<<gHd, 256>>>(x, wqt, bq, nullptr, q, BSR, HD, HD);
    gemm_mma<0><<<gHd, 256>>>(x, wkt, bk, nullptr, k, BSR, HD, HD);
    gemm_mma<0><<<gHd, 256>>>(x, wvt, bv, nullptr, v, BSR, HD, HD);

    // RoPE
    rope_kernel<<<(BSR * (HD / 2)) / 256, 256>>>(q, k);

    // Flash attention on tensor cores -> ctx
    attn_mma<<<dim3(SS / 128, BB * NHH), 256, ATT_SMEM>>>(q, k, v, ctx);

    // O projection + residual(x) -> r1 ; LN -> h
    gemm_mma<0><<<gHd, 256>>>(ctx, wot, bo, x, r1, BSR, HD, HD);
    ln_kernel<<<BSR, 256>>>(r1, g1, beta1, h);

    // FFN
    gemm_mma<1><<<gFf, 256>>>(h,  w1t, b1, nullptr, ff, BSR, FFD, HD);
    gemm_mma<0><<<gHd, 256>>>(ff, w2t, b2, h,       r2, BSR, HD, FFD);

    // final LN -> out
    ln_kernel<<<BSR, 256>>>(r2, g2, beta2, out);
}

// round 7
// speedup vs baseline: 3.6214x; 1.2824x over previous
#include <cuda_runtime.h>
#include <cuda_bf16.h>
#include <math.h>
#include <stdint.h>

// Problem constants
#define BB   4
#define SS   2048
#define HD   1024
#define NHH  16
#define DD   64
#define FFD  4096
#define BSR  (BB*SS)          // 8192 rows
#define LOG2E 1.4426950408889634f

// ---------------- scratch (device globals: no allocation allowed) ----------
__device__ float g_q  [BSR * HD];
__device__ float g_k  [BSR * HD];
__device__ float g_v  [BSR * HD];
__device__ float g_ctx[BSR * HD];
__device__ float g_r1 [BSR * HD];
__device__ float g_h  [BSR * HD];
__device__ float g_ff [BSR * FFD];
__device__ float g_r2 [BSR * HD];
// transposed (N,K) tf32-rounded weights
__device__ float g_wqt[HD * HD];
__device__ float g_wkt[HD * HD];
__device__ float g_wvt[HD * HD];
__device__ float g_wot[HD * HD];
__device__ float g_w1t[FFD * HD];
__device__ float g_w2t[HD * FFD];
// rope inverse-frequency table
__device__ float g_ropeinv[32];

__device__ __forceinline__ float tf32r(float x) {
    float r;
    asm("cvt.rna.tf32.f32 %0, %1;" : "=f"(r) : "f"(x));
    return r;
}
__device__ __forceinline__ uint32_t smem_u32(const void* p) {
    uint32_t a;
    asm("{ .reg .u64 t; cvta.to.shared.u64 t, %1; cvt.u32.u64 %0, t; }" : "=r"(a) : "l"(p));
    return a;
}
__device__ __forceinline__ void cp_async16(uint32_t saddr, const void* g) {
    asm volatile("cp.async.cg.shared.global [%0], [%1], 16;" :: "r"(saddr), "l"(g));
}
__device__ __forceinline__ void cp_commit() {
    asm volatile("cp.async.commit_group;" ::: "memory");
}
template<int N> __device__ __forceinline__ void cp_wait() {
    asm volatile("cp.async.wait_group %0;" :: "n"(N) : "memory");
}

// fast exp2 on the fma/alu pipes (valid for x <= ~0; clamps at -126)
__device__ __forceinline__ float fexp2(float x) {
    x = fmaxf(x, -126.f);
    const float k = x + 12582912.f;              // 1.5*2^23: rint via magic
    const int   ik = __float_as_int(k) - 0x4B400000;
    const float f = x - (k - 12582912.f);        // f in [-0.5, 0.5]
    float p = 9.6181291e-3f;                     // Taylor of 2^f
    p = fmaf(p, f, 5.5504109e-2f);
    p = fmaf(p, f, 2.4022651e-1f);
    p = fmaf(p, f, 6.9314718e-1f);
    p = fmaf(p, f, 1.0f);
    return __int_as_float(__float_as_int(p) + (ik << 23));
}

__device__ __forceinline__ void mma_tf32_16x8x8(float* c, const uint32_t* a, const uint32_t* b) {
    asm volatile(
        "mma.sync.aligned.m16n8k8.row.col.f32.tf32.tf32.f32 "
        "{%0,%1,%2,%3}, {%4,%5,%6,%7}, {%8,%9}, {%0,%1,%2,%3};"
        : "+f"(c[0]), "+f"(c[1]), "+f"(c[2]), "+f"(c[3])
        : "r"(a[0]), "r"(a[1]), "r"(a[2]), "r"(a[3]), "r"(b[0]), "r"(b[1]));
}

// =================== tf32 mma.sync GEMM (cp.async pipeline) ================
// C[M,N] = A[M,K] @ Bt[N,K]^T (+bias, +add, optional gelu)
// BM=BN=128, BK=32, 256 threads (8 warps), warp tile 64x32, 2-stage cp.async.
#define AST 36                 // smem row stride in floats (32 + 4 pad = 144B)
#define GBUF (128 * AST)       // floats per stage per operand

__device__ __forceinline__ void stage_copy(const float* __restrict__ A,
                                           const float* __restrict__ Bt,
                                           int K, int crow, int ccol, int k0,
                                           float* sa, float* sb, int tid)
{
    const int r0 = tid >> 3;
    const int c  = (tid & 7) * 4;
    #pragma unroll
    for (int i = 0; i < 4; i++) {
        const int row = i * 32 + r0;
        cp_async16(smem_u32(sa + row * AST + c), A  + (size_t)(crow + row) * K + k0 + c);
        cp_async16(smem_u32(sb + row * AST + c), Bt + (size_t)(ccol + row) * K + k0 + c);
    }
}

template<int EPI>   // 0 = none, 1 = gelu(tanh)
__global__ __launch_bounds__(256)
void gemm_mma(const float* __restrict__ A, const float* __restrict__ Bt,
              const float* __restrict__ bias, const float* __restrict__ add,
              float* __restrict__ C, int M, int N, int K)
{
    extern __shared__ float smem[];
    float* As = smem;              // [2][GBUF]
    float* Bs = smem + 2 * GBUF;   // [2][GBUF]

    const int tid  = threadIdx.x;
    const int wid  = tid >> 5;
    const int lane = tid & 31;
    const int g    = lane >> 2;       // 0..7
    const int t    = lane & 3;        // 0..3

    const int crow = blockIdx.y * 128;
    const int ccol = blockIdx.x * 128;

    const int rb = (wid & 1) * 64;    // warp row group
    const int cb = (wid >> 1) * 32;   // warp col group

    float acc[4][4][4];
    #pragma unroll
    for (int i = 0; i < 4; i++)
        #pragma unroll
        for (int j = 0; j < 4; j++)
            #pragma unroll
            for (int e = 0; e < 4; e++) acc[i][j][e] = 0.f;

    const int niter = K >> 5;   // BK=32; K is 1024 or 4096 -> niter >= 32

    stage_copy(A, Bt, K, crow, ccol, 0,  As,        Bs,        tid);
    cp_commit();
    stage_copy(A, Bt, K, crow, ccol, 32, As + GBUF, Bs + GBUF, tid);
    cp_commit();

    for (int it = 0; it < niter; ++it) {
        cp_wait<1>();
        __syncthreads();

        const float* as = As + (it & 1) * GBUF;
        const float* bs = Bs + (it & 1) * GBUF;
        #pragma unroll
        for (int kk = 0; kk < 32; kk += 8) {
            uint32_t af[4][4], bf[4][2];
            #pragma unroll
            for (int mt = 0; mt < 4; mt++) {
                const int base = (rb + mt * 16 + g) * AST + kk + t;
                af[mt][0] = __float_as_uint(as[base]);
                af[mt][1] = __float_as_uint(as[base + 8 * AST]);
                af[mt][2] = __float_as_uint(as[base + 4]);
                af[mt][3] = __float_as_uint(as[base + 8 * AST + 4]);
            }
            #pragma unroll
            for (int nt = 0; nt < 4; nt++) {
                const int base = (cb + nt * 8 + g) * AST + kk + t;
                bf[nt][0] = __float_as_uint(bs[base]);
                bf[nt][1] = __float_as_uint(bs[base + 4]);
            }
            #pragma unroll
            for (int mt = 0; mt < 4; mt++)
                #pragma unroll
                for (int nt = 0; nt < 4; nt++)
                    mma_tf32_16x8x8(acc[mt][nt], af[mt], bf[nt]);
        }

        __syncthreads();
        if (it + 2 < niter)
            stage_copy(A, Bt, K, crow, ccol, (it + 2) << 5,
                       As + (it & 1) * GBUF, Bs + (it & 1) * GBUF, tid);
        cp_commit();   // commit (possibly empty) to keep group counts uniform
    }

    // epilogue
    #pragma unroll
    for (int mt = 0; mt < 4; mt++) {
        #pragma unroll
        for (int half = 0; half < 2; half++) {
            const int r = crow + rb + mt * 16 + g + half * 8;
            #pragma unroll
            for (int nt = 0; nt < 4; nt++) {
                const int c0 = ccol + cb + nt * 8 + t * 2;
                float v0 = acc[mt][nt][half * 2 + 0] + bias[c0 + 0];
                float v1 = acc[mt][nt][half * 2 + 1] + bias[c0 + 1];
                if (add) {
                    const float2 a2 = *(const float2*)(add + (size_t)r * N + c0);
                    v0 += a2.x; v1 += a2.y;
                }
                if (EPI == 1) {
                    v0 = 0.5f * v0 * (1.f + tanhf(0.7978845608028654f * (v0 + 0.044715f * v0 * v0 * v0)));
                    v1 = 0.5f * v1 * (1.f + tanhf(0.7978845608028654f * (v1 + 0.044715f * v1 * v1 * v1)));
                }
                *(float2*)(C + (size_t)r * N + c0) = make_float2(v0, v1);
            }
        }
    }
}

// ------------- weight transpose + tf32 rounding: in[R,C] -> out[C,R] -------
__global__ __launch_bounds__(256)
void transpose_rna(const float* __restrict__ in, float* __restrict__ out, int R, int C)
{
    __shared__ float t[32][33];
    const int bx = blockIdx.x * 32, by = blockIdx.y * 32;
    const int tx = threadIdx.x, ty = threadIdx.y;
    #pragma unroll
    for (int i = 0; i < 32; i += 8)
        t[ty + i][tx] = in[(size_t)(by + ty + i) * C + bx + tx];
    __syncthreads();
    #pragma unroll
    for (int i = 0; i < 32; i += 8)
        out[(size_t)(bx + ty + i) * R + by + tx] = tf32r(t[tx][ty + i]);
}

// ---------------- RoPE -----------------------------------------------------
__global__ void rope_tab_kernel() {
    const int i = threadIdx.x;
    if (i < 32) g_ropeinv[i] = (float)pow(10000.0, -((double)(2 * i)) / 64.0);
}
__global__ __launch_bounds__(256)
void rope_kernel(float* __restrict__ q, float* __restrict__ k)
{
    const int idx = blockIdx.x * blockDim.x + threadIdx.x;   // one pair
    if (idx >= BSR * (HD / 2)) return;
    const int row = idx >> 9;
    const int p   = idx & 511;
    const int s   = row & (SS - 1);
    const int i   = p & 31;

    const float ang = (float)s * g_ropeinv[i];
    float sn, c;
    sincosf(ang, &sn, &c);

    float2* qp = (float2*)(q + (size_t)row * HD) + p;
    float2* kp = (float2*)(k + (size_t)row * HD) + p;
    const float2 qv = *qp, kv = *kp;
    float2 qo, ko;
    qo.x = qv.x * c - qv.y * sn;  qo.y = qv.y * c + qv.x * sn;
    ko.x = kv.x * c - kv.y * sn;  ko.y = kv.y * c + kv.x * sn;
    *qp = qo; *kp = ko;
}

// ============== Flash attention on tensor cores (tf32 mma.sync) ============
#define ATS 68
__global__ __launch_bounds__(256)
void attn_mma(const float* __restrict__ Q, const float* __restrict__ Kg,
              const float* __restrict__ Vg, float* __restrict__ O)
{
    extern __shared__ float sm[];
    float* Ks = sm;                   // [64][ATS]
    float* Vt = sm + 64 * ATS;        // [64][ATS]  (transposed V: [d][j])
    float* Ps = sm + 128 * ATS;       // [128][ATS]

    const int tid  = threadIdx.x;
    const int wid  = tid >> 5;
    const int lane = tid & 31;
    const int g    = lane >> 2;
    const int t    = lane & 3;
    const int rb   = wid * 16;

    const int bh = blockIdx.y;
    const int b  = bh >> 4;
    const int h  = bh & 15;
    const int q0 = blockIdx.x * 128;

    const float qscale = 0.125f * LOG2E;

    const float* qbase = Q + ((size_t)(b * SS + q0)) * HD + h * DD;
    #pragma unroll
    for (int l = 0; l < 8; l++) {
        const int idx = l * 256 + tid;
        const int r = idx >> 4, c4 = idx & 15;
        const float4 v4 = *(const float4*)(qbase + (size_t)r * HD + c4 * 4);
        float* d = Ps + r * ATS + c4 * 4;
        d[0] = tf32r(v4.x * qscale); d[1] = tf32r(v4.y * qscale);
        d[2] = tf32r(v4.z * qscale); d[3] = tf32r(v4.w * qscale);
    }
    __syncthreads();

    uint32_t qf[8][4];
    #pragma unroll
    for (int kk = 0; kk < 8; kk++) {
        const int base = (rb + g) * ATS + kk * 8 + t;
        qf[kk][0] = __float_as_uint(Ps[base]);
        qf[kk][1] = __float_as_uint(Ps[base + 8 * ATS]);
        qf[kk][2] = __float_as_uint(Ps[base + 4]);
        qf[kk][3] = __float_as_uint(Ps[base + 8 * ATS + 4]);
    }

    float acc[8][4];
    #pragma unroll
    for (int nt = 0; nt < 8; nt++)
        #pragma unroll
        for (int e = 0; e < 4; e++) acc[nt][e] = 0.f;
    float m0 = -1e30f, m1 = -1e30f, l0 = 0.f, l1 = 0.f;

    const float* kbase = Kg + ((size_t)b * SS) * HD + h * DD;
    const float* vbase = Vg + ((size_t)b * SS) * HD + h * DD;

    for (int kt = 0; kt < SS; kt += 64) {
        __syncthreads();
        #pragma unroll
        for (int l = 0; l < 4; l++) {
            const int idx = l * 256 + tid;
            const int r = idx >> 4, c4 = idx & 15;
            const float4 k4 = *(const float4*)(kbase + (size_t)(kt + r) * HD + c4 * 4);
            float* d = Ks + r * ATS + c4 * 4;
            d[0] = tf32r(k4.x); d[1] = tf32r(k4.y); d[2] = tf32r(k4.z); d[3] = tf32r(k4.w);
            const float4 v4 = *(const float4*)(vbase + (size_t)(kt + r) * HD + c4 * 4);
            Vt[(c4 * 4 + 0) * ATS + r] = tf32r(v4.x);
            Vt[(c4 * 4 + 1) * ATS + r] = tf32r(v4.y);
            Vt[(c4 * 4 + 2) * ATS + r] = tf32r(v4.z);
            Vt[(c4 * 4 + 3) * ATS + r] = tf32r(v4.w);
        }
        __syncthreads();

        float s[8][4];
        #pragma unroll
        for (int nt = 0; nt < 8; nt++)
            #pragma unroll
            for (int e = 0; e < 4; e++) s[nt][e] = 0.f;
        #pragma unroll
        for (int kk = 0; kk < 8; kk++) {
            uint32_t bf[8][2];
            #pragma unroll
            for (int nt = 0; nt < 8; nt++) {
                const int base = (nt * 8 + g) * ATS + kk * 8 + t;
                bf[nt][0] = __float_as_uint(Ks[base]);
                bf[nt][1] = __float_as_uint(Ks[base + 4]);
            }
            #pragma unroll
            for (int nt = 0; nt < 8; nt++)
                mma_tf32_16x8x8(s[nt], qf[kk], bf[nt]);
        }

        float rm0 = s[0][0], rm1 = s[0][2];
        #pragma unroll
        for (int nt = 0; nt < 8; nt++) {
            rm0 = fmaxf(rm0, fmaxf(s[nt][0], s[nt][1]));
            rm1 = fmaxf(rm1, fmaxf(s[nt][2], s[nt][3]));
        }
        rm0 = fmaxf(rm0, __shfl_xor_sync(0xffffffffu, rm0, 1));
        rm0 = fmaxf(rm0, __shfl_xor_sync(0xffffffffu, rm0, 2));
        rm1 = fmaxf(rm1, __shfl_xor_sync(0xffffffffu, rm1, 1));
        rm1 = fmaxf(rm1, __shfl_xor_sync(0xffffffffu, rm1, 2));
        const float mt0 = fmaxf(m0, rm0);
        const float mt1 = fmaxf(m1, rm1);
        if (mt0 > m0) {
            const float c0 = fexp2(m0 - mt0);
            l0 *= c0;
            #pragma unroll
            for (int nt = 0; nt < 8; nt++) { acc[nt][0] *= c0; acc[nt][1] *= c0; }
            m0 = mt0;
        }
        if (mt1 > m1) {
            const float c1 = fexp2(m1 - mt1);
            l1 *= c1;
            #pragma unroll
            for (int nt = 0; nt < 8; nt++) { acc[nt][2] *= c1; acc[nt][3] *= c1; }
            m1 = mt1;
        }

        float ps0 = 0.f, ps1 = 0.f;
        #pragma unroll
        for (int nt = 0; nt < 8; nt++) {
            const float p00 = tf32r(fexp2(s[nt][0] - m0));
            const float p01 = tf32r(fexp2(s[nt][1] - m0));
            const float p10 = tf32r(fexp2(s[nt][2] - m1));
            const float p11 = tf32r(fexp2(s[nt][3] - m1));
            ps0 += p00 + p01;
            ps1 += p10 + p11;
            *(float2*)&Ps[(rb + g) * ATS + nt * 8 + 2 * t]     = make_float2(p00, p01);
            *(float2*)&Ps[(rb + g + 8) * ATS + nt * 8 + 2 * t] = make_float2(p10, p11);
        }
        ps0 += __shfl_xor_sync(0xffffffffu, ps0, 1);
        ps0 += __shfl_xor_sync(0xffffffffu, ps0, 2);
        ps1 += __shfl_xor_sync(0xffffffffu, ps1, 1);
        ps1 += __shfl_xor_sync(0xffffffffu, ps1, 2);
        l0 += ps0;
        l1 += ps1;
        __syncwarp();

        #pragma unroll
        for (int kk = 0; kk < 8; kk++) {
            uint32_t af[4];
            const int base = (rb + g) * ATS + kk * 8 + t;
            af[0] = __float_as_uint(Ps[base]);
            af[1] = __float_as_uint(Ps[base + 8 * ATS]);
            af[2] = __float_as_uint(Ps[base + 4]);
            af[3] = __float_as_uint(Ps[base + 8 * ATS + 4]);
            #pragma unroll
            for (int nt = 0; nt < 8; nt++) {
                uint32_t bf[2];
                const int vb = (nt * 8 + g) * ATS + kk * 8 + t;
                bf[0] = __float_as_uint(Vt[vb]);
                bf[1] = __float_as_uint(Vt[vb + 4]);
                mma_tf32_16x8x8(acc[nt], af, bf);
            }
        }
    }

    const float i0 = 1.f / l0;
    const float i1 = 1.f / l1;
    const int r0 = q0 + rb + g;
    const int r1 = r0 + 8;
    float* o0 = O + ((size_t)(b * SS + r0)) * HD + h * DD;
    float* o1 = O + ((size_t)(b * SS + r1)) * HD + h * DD;
    #pragma unroll
    for (int nt = 0; nt < 8; nt++) {
        *(float2*)(o0 + nt * 8 + 2 * t) = make_float2(acc[nt][0] * i0, acc[nt][1] * i0);
        *(float2*)(o1 + nt * 8 + 2 * t) = make_float2(acc[nt][2] * i1, acc[nt][3] * i1);
    }
}

// ---------------- LayerNorm over last dim (1024), eps=1e-12 ----------------
__global__ __launch_bounds__(256)
void ln_kernel(const float* __restrict__ in, const float* __restrict__ gamma,
               const float* __restrict__ beta, float* __restrict__ out)
{
    const int row = blockIdx.x;
    const int tid = threadIdx.x;
    const float4 xv = ((const float4*)(in + (size_t)row * HD))[tid];

    __shared__ float red[32];
    float s = xv.x + xv.y + xv.z + xv.w;
    #pragma unroll
    for (int o = 16; o > 0; o >>= 1) s += __shfl_xor_sync(0xffffffffu, s, o);
    if ((tid & 31) == 0) red[tid >> 5] = s;
    __syncthreads();
    if (tid < 32) {
        float t = (tid < 8) ? red[tid] : 0.f;
        #pragma unroll
        for (int o = 4; o > 0; o >>= 1) t += __shfl_xor_sync(0xffffffffu, t, o);
        if (tid == 0) red[0] = t;
    }
    __syncthreads();
    const float mu = red[0] * (1.f / 1024.f);
    __syncthreads();

    const float dx = xv.x - mu, dy = xv.y - mu, dz = xv.z - mu, dw = xv.w - mu;
    float sq = dx*dx + dy*dy + dz*dz + dw*dw;
    #pragma unroll
    for (int o = 16; o > 0; o >>= 1) sq += __shfl_xor_sync(0xffffffffu, sq, o);
    if ((tid & 31) == 0) red[tid >> 5] = sq;
    __syncthreads();
    if (tid < 32) {
        float t = (tid < 8) ? red[tid] : 0.f;
        #pragma unroll
        for (int o = 4; o > 0; o >>= 1) t += __shfl_xor_sync(0xffffffffu, t, o);
        if (tid == 0) red[0] = t;
    }
    __syncthreads();
    const float var  = red[0] * (1.f / 1024.f);
    const float rstd = rsqrtf(var + 1e-12f);

    const float4 gv = ((const float4*)gamma)[tid];
    const float4 bv = ((const float4*)beta )[tid];
    float4 ov;
    ov.x = dx * rstd * gv.x + bv.x;
    ov.y = dy * rstd * gv.y + bv.y;
    ov.z = dz * rstd * gv.z + bv.z;
    ov.w = dw * rstd * gv.w + bv.w;
    ((float4*)(out + (size_t)row * HD))[tid] = ov;
}

// ---------------- launch ----------------------------------------------------
extern "C" void kernel_launch(void* const* d_in, const int* in_sizes, int n_in,
                              void* d_out, int out_size)
{
    const float* x     = (const float*)d_in[0];
    const float* Wq    = (const float*)d_in[1];
    const float* bq    = (const float*)d_in[2];
    const float* Wk    = (const float*)d_in[3];
    const float* bk    = (const float*)d_in[4];
    const float* Wv    = (const float*)d_in[5];
    const float* bv    = (const float*)d_in[6];
    const float* Wo    = (const float*)d_in[7];
    const float* bo    = (const float*)d_in[8];
    const float* g1    = (const float*)d_in[9];
    const float* beta1 = (const float*)d_in[10];
    const float* W1    = (const float*)d_in[11];
    const float* b1    = (const float*)d_in[12];
    const float* W2    = (const float*)d_in[13];
    const float* b2    = (const float*)d_in[14];
    const float* g2    = (const float*)d_in[15];
    const float* beta2 = (const float*)d_in[16];
    float* out = (float*)d_out;

    float *q, *k, *v, *ctx, *r1, *h, *ff, *r2;
    float *wqt, *wkt, *wvt, *wot, *w1t, *w2t;
    cudaGetSymbolAddress((void**)&q,   g_q);
    cudaGetSymbolAddress((void**)&k,   g_k);
    cudaGetSymbolAddress((void**)&v,   g_v);
    cudaGetSymbolAddress((void**)&ctx, g_ctx);
    cudaGetSymbolAddress((void**)&r1,  g_r1);
    cudaGetSymbolAddress((void**)&h,   g_h);
    cudaGetSymbolAddress((void**)&ff,  g_ff);
    cudaGetSymbolAddress((void**)&r2,  g_r2);
    cudaGetSymbolAddress((void**)&wqt, g_wqt);
    cudaGetSymbolAddress((void**)&wkt, g_wkt);
    cudaGetSymbolAddress((void**)&wvt, g_wvt);
    cudaGetSymbolAddress((void**)&wot, g_wot);
    cudaGetSymbolAddress((void**)&w1t, g_w1t);
    cudaGetSymbolAddress((void**)&w2t, g_w2t);

    const int GEMM_SMEM = 4 * GBUF * 4;   // 73728 B
    const int ATT_SMEM  = 256 * ATS * 4;  // 69632 B
    cudaFuncSetAttribute(gemm_mma<0>, cudaFuncAttributeMaxDynamicSharedMemorySize, GEMM_SMEM);
    cudaFuncSetAttribute(gemm_mma<1>, cudaFuncAttributeMaxDynamicSharedMemorySize, GEMM_SMEM);
    cudaFuncSetAttribute(attn_mma, cudaFuncAttributeMaxDynamicSharedMemorySize, ATT_SMEM);

    // rope table + weight transposes (tf32-rounded, [N,K] layout)
    rope_tab_kernel<<<1, 32>>>();
    const dim3 tb(32, 8);
    transpose_rna<<<dim3(HD / 32,  HD / 32),  tb>>>(Wq, wqt, HD,  HD);
    transpose_rna<<<dim3(HD / 32,  HD / 32),  tb>>>(Wk, wkt, HD,  HD);
    transpose_rna<<<dim3(HD / 32,  HD / 32),  tb>>>(Wv, wvt, HD,  HD);
    transpose_rna<<<dim3(HD / 32,  HD / 32),  tb>>>(Wo, wot, HD,  HD);
    transpose_rna<<<dim3(FFD / 32, HD / 32),  tb>>>(W1, w1t, HD,  FFD);
    transpose_rna<<<dim3(HD / 32,  FFD / 32), tb>>>(W2, w2t, FFD, HD);

    const dim3 gHd(HD  / 128, BSR / 128);   // (8, 64)
    const dim3 gFf(FFD / 128, BSR / 128);   // (32, 64)

    // QKV projections (tf32 mma.sync, cp.async pipeline)
    gemm_mma<0><<<gHd, 256, GEMM_SMEM>>>(x, wqt, bq, nullptr, q, BSR, HD, HD);
    gemm_mma<0><<<gHd, 256, GEMM_SMEM>>>(x, wkt, bk, nullptr, k, BSR, HD, HD);
    gemm_mma<0><<<gHd, 256, GEMM_SMEM>>>(x, wvt, bv, nullptr, v, BSR, HD, HD);

    // RoPE
    rope_kernel<<<(BSR * (HD / 2)) / 256, 256>>>(q, k);

    // Flash attention on tensor cores -> ctx
    attn_mma<<<dim3(SS / 128, BB * NHH), 256, ATT_SMEM>>>(q, k, v, ctx);

    // O projection + residual(x) -> r1 ; LN -> h
    gemm_mma<0><<<gHd, 256, GEMM_SMEM>>>(ctx, wot, bo, x, r1, BSR, HD, HD);
    ln_kernel<<<BSR, 256>>>(r1, g1, beta1, h);

    // FFN
    gemm_mma<1><<<gFf, 256, GEMM_SMEM>>>(h,  w1t, b1, nullptr, ff, BSR, FFD, HD);
    gemm_mma<0><<<gHd, 256, GEMM_SMEM>>>(ff, w2t, b2, h,       r2, BSR, HD, FFD);

    // final LN -> out
    ln_kernel<<<BSR, 256>>>(r2, g2, beta2, out);
}

// round 8
// speedup vs baseline: 3.7914x; 1.0469x over previous
#include <cuda_runtime.h>
#include <cuda_bf16.h>
#include <math.h>
#include <stdint.h>

// Problem constants
#define BB   4
#define SS   2048
#define HD   1024
#define NHH  16
#define DD   64
#define FFD  4096
#define BSR  (BB*SS)          // 8192 rows
#define LOG2E 1.4426950408889634f

// ---------------- scratch (device globals: no allocation allowed) ----------
__device__ float g_q  [BSR * HD];
__device__ float g_k  [BSR * HD];
__device__ float g_v  [BSR * HD];
__device__ float g_ctx[BSR * HD];
__device__ float g_r1 [BSR * HD];
__device__ float g_h  [BSR * HD];
__device__ float g_ff [BSR * FFD];
__device__ float g_r2 [BSR * HD];
// packed transposed (N,K) tf32-rounded weights
__device__ float g_wqkvt[3 * HD * HD];     // rows 0..1023 Wq^T, 1024.. Wk^T, 2048.. Wv^T
__device__ float g_bqkv [3 * HD];
__device__ float g_wot[HD * HD];
__device__ float g_w1t[FFD * HD];
__device__ float g_w2t[HD * FFD];
// rope cos/sin table [S][32]
__device__ float2 g_ropetab[SS * 32];

__device__ __forceinline__ float tf32r(float x) {
    float r;
    asm("cvt.rna.tf32.f32 %0, %1;" : "=f"(r) : "f"(x));
    return r;
}
__device__ __forceinline__ float tanh_fast(float x) {
    float y;
    asm("tanh.approx.f32 %0, %1;" : "=f"(y) : "f"(x));
    return y;
}
__device__ __forceinline__ uint32_t smem_u32(const void* p) {
    uint32_t a;
    asm("{ .reg .u64 t; cvta.to.shared.u64 t, %1; cvt.u32.u64 %0, t; }" : "=r"(a) : "l"(p));
    return a;
}
__device__ __forceinline__ void cp_async16(uint32_t saddr, const void* g) {
    asm volatile("cp.async.cg.shared.global [%0], [%1], 16;" :: "r"(saddr), "l"(g));
}
__device__ __forceinline__ void cp_commit() {
    asm volatile("cp.async.commit_group;" ::: "memory");
}
template<int N> __device__ __forceinline__ void cp_wait() {
    asm volatile("cp.async.wait_group %0;" :: "n"(N) : "memory");
}

// fast exp2 on the fma/alu pipes (valid for x <= ~0; clamps at -126)
__device__ __forceinline__ float fexp2(float x) {
    x = fmaxf(x, -126.f);
    const float k = x + 12582912.f;
    const int   ik = __float_as_int(k) - 0x4B400000;
    const float f = x - (k - 12582912.f);
    float p = 9.6181291e-3f;
    p = fmaf(p, f, 5.5504109e-2f);
    p = fmaf(p, f, 2.4022651e-1f);
    p = fmaf(p, f, 6.9314718e-1f);
    p = fmaf(p, f, 1.0f);
    return __int_as_float(__float_as_int(p) + (ik << 23));
}

__device__ __forceinline__ void mma_tf32_16x8x8(float* c, const uint32_t* a, const uint32_t* b) {
    asm volatile(
        "mma.sync.aligned.m16n8k8.row.col.f32.tf32.tf32.f32 "
        "{%0,%1,%2,%3}, {%4,%5,%6,%7}, {%8,%9}, {%0,%1,%2,%3};"
        : "+f"(c[0]), "+f"(c[1]), "+f"(c[2]), "+f"(c[3])
        : "r"(a[0]), "r"(a[1]), "r"(a[2]), "r"(a[3]), "r"(b[0]), "r"(b[1]));
}

// =================== tf32 mma.sync GEMM (cp.async pipeline) ================
// EPI: 0 = bias(+add), 1 = bias+gelu, 2 = fused QKV + RoPE
// BM=BN=128, BK=32, 256 threads (8 warps), warp tile 64x32, 2-stage cp.async.
#define AST 36
#define GBUF (128 * AST)

__device__ __forceinline__ void stage_copy(const float* __restrict__ A,
                                           const float* __restrict__ Bt,
                                           int K, int crow, int ccol, int k0,
                                           float* sa, float* sb, int tid)
{
    const int r0 = tid >> 3;
    const int c  = (tid & 7) * 4;
    #pragma unroll
    for (int i = 0; i < 4; i++) {
        const int row = i * 32 + r0;
        cp_async16(smem_u32(sa + row * AST + c), A  + (size_t)(crow + row) * K + k0 + c);
        cp_async16(smem_u32(sb + row * AST + c), Bt + (size_t)(ccol + row) * K + k0 + c);
    }
}

template<int EPI>
__global__ __launch_bounds__(256)
void gemm_mma(const float* __restrict__ A, const float* __restrict__ Bt,
              const float* __restrict__ bias, const float* __restrict__ add,
              float* __restrict__ C, int M, int N, int K,
              float* __restrict__ Ck = nullptr, float* __restrict__ Cv = nullptr)
{
    extern __shared__ float smem[];
    float* As = smem;
    float* Bs = smem + 2 * GBUF;

    const int tid  = threadIdx.x;
    const int wid  = tid >> 5;
    const int lane = tid & 31;
    const int g    = lane >> 2;
    const int t    = lane & 3;

    const int crow = blockIdx.y * 128;
    const int ccol = blockIdx.x * 128;       // global col (0..3071 in EPI=2)

    const int rb = (wid & 1) * 64;
    const int cb = (wid >> 1) * 32;

    float acc[4][4][4];
    #pragma unroll
    for (int i = 0; i < 4; i++)
        #pragma unroll
        for (int j = 0; j < 4; j++)
            #pragma unroll
            for (int e = 0; e < 4; e++) acc[i][j][e] = 0.f;

    const int niter = K >> 5;

    stage_copy(A, Bt, K, crow, ccol, 0,  As,        Bs,        tid);
    cp_commit();
    stage_copy(A, Bt, K, crow, ccol, 32, As + GBUF, Bs + GBUF, tid);
    cp_commit();

    for (int it = 0; it < niter; ++it) {
        cp_wait<1>();
        __syncthreads();

        const float* as = As + (it & 1) * GBUF;
        const float* bs = Bs + (it & 1) * GBUF;
        #pragma unroll
        for (int kk = 0; kk < 32; kk += 8) {
            uint32_t af[4][4], bf[4][2];
            #pragma unroll
            for (int mt = 0; mt < 4; mt++) {
                const int base = (rb + mt * 16 + g) * AST + kk + t;
                af[mt][0] = __float_as_uint(as[base]);
                af[mt][1] = __float_as_uint(as[base + 8 * AST]);
                af[mt][2] = __float_as_uint(as[base + 4]);
                af[mt][3] = __float_as_uint(as[base + 8 * AST + 4]);
            }
            #pragma unroll
            for (int nt = 0; nt < 4; nt++) {
                const int base = (cb + nt * 8 + g) * AST + kk + t;
                bf[nt][0] = __float_as_uint(bs[base]);
                bf[nt][1] = __float_as_uint(bs[base + 4]);
            }
            #pragma unroll
            for (int mt = 0; mt < 4; mt++)
                #pragma unroll
                for (int nt = 0; nt < 4; nt++)
                    mma_tf32_16x8x8(acc[mt][nt], af[mt], bf[nt]);
        }

        __syncthreads();
        if (it + 2 < niter)
            stage_copy(A, Bt, K, crow, ccol, (it + 2) << 5,
                       As + (it & 1) * GBUF, Bs + (it & 1) * GBUF, tid);
        cp_commit();
    }

    // -------- epilogue --------
    float* Cout = C;
    int colmask = ~0;
    bool dorope = false;
    if (EPI == 2) {
        const int sel = ccol >> 10;                 // 0=q 1=k 2=v (128-col tile never straddles)
        Cout = (sel == 0) ? C : (sel == 1 ? Ck : Cv);
        colmask = 1023;
        dorope = (sel < 2);
    }

    #pragma unroll
    for (int mt = 0; mt < 4; mt++) {
        #pragma unroll
        for (int half = 0; half < 2; half++) {
            const int r = crow + rb + mt * 16 + g + half * 8;
            const int s = r & (SS - 1);
            #pragma unroll
            for (int nt = 0; nt < 4; nt++) {
                const int cg = ccol + cb + nt * 8 + t * 2;      // global col
                float v0 = acc[mt][nt][half * 2 + 0] + bias[cg + 0];
                float v1 = acc[mt][nt][half * 2 + 1] + bias[cg + 1];
                if (EPI == 0 || EPI == 1) {
                    if (add) {
                        const float2 a2 = *(const float2*)(add + (size_t)r * N + cg);
                        v0 += a2.x; v1 += a2.y;
                    }
                    if (EPI == 1) {
                        const float t0 = tanh_fast(0.7978845608028654f * (v0 + 0.044715f * v0 * v0 * v0));
                        const float t1 = tanh_fast(0.7978845608028654f * (v1 + 0.044715f * v1 * v1 * v1));
                        v0 = 0.5f * v0 * (1.f + t0);
                        v1 = 0.5f * v1 * (1.f + t1);
                    }
                    *(float2*)(C + (size_t)r * N + cg) = make_float2(v0, v1);
                } else {
                    const int cl = cg & colmask;               // col within matrix
                    if (dorope) {
                        const int i = (cl & 63) >> 1;          // pair index in head
                        const float2 cs = g_ropetab[s * 32 + i];
                        const float n0 = v0 * cs.x - v1 * cs.y;
                        const float n1 = v1 * cs.x + v0 * cs.y;
                        v0 = n0; v1 = n1;
                    }
                    *(float2*)(Cout + (size_t)r * HD + cl) = make_float2(v0, v1);
                }
            }
        }
    }
}

// ------------- weight transpose + tf32 rounding: in[R,C] -> out[C,R] -------
__global__ __launch_bounds__(256)
void transpose_rna(const float* __restrict__ in, float* __restrict__ out, int R, int C)
{
    __shared__ float t[32][33];
    const int bx = blockIdx.x * 32, by = blockIdx.y * 32;
    const int tx = threadIdx.x, ty = threadIdx.y;
    #pragma unroll
    for (int i = 0; i < 32; i += 8)
        t[ty + i][tx] = in[(size_t)(by + ty + i) * C + bx + tx];
    __syncthreads();
    #pragma unroll
    for (int i = 0; i < 32; i += 8)
        out[(size_t)(bx + ty + i) * R + by + tx] = tf32r(t[tx][ty + i]);
}

// ---------------- rope table + bias pack -----------------------------------
__global__ void rope_tab_kernel() {
    const int s = blockIdx.x;
    const int i = threadIdx.x;        // 0..31
    const float inv = (float)pow(10000.0, -((double)(2 * i)) / 64.0);
    float sn, c;
    sincosf((float)s * inv, &sn, &c);
    g_ropetab[s * 32 + i] = make_float2(c, sn);
}
__global__ void pack_bias_kernel(const float* bq, const float* bk, const float* bv) {
    const int i = blockIdx.x * blockDim.x + threadIdx.x;
    if (i < HD)           g_bqkv[i] = bq[i];
    else if (i < 2 * HD)  g_bqkv[i] = bk[i - HD];
    else if (i < 3 * HD)  g_bqkv[i] = bv[i - 2 * HD];
}

// ============== Flash attention on tensor cores (tf32 mma.sync) ============
#define ATS 68
__global__ __launch_bounds__(256)
void attn_mma(const float* __restrict__ Q, const float* __restrict__ Kg,
              const float* __restrict__ Vg, float* __restrict__ O)
{
    extern __shared__ float sm[];
    float* Ks = sm;
    float* Vt = sm + 64 * ATS;
    float* Ps = sm + 128 * ATS;

    const int tid  = threadIdx.x;
    const int wid  = tid >> 5;
    const int lane = tid & 31;
    const int g    = lane >> 2;
    const int t    = lane & 3;
    const int rb   = wid * 16;

    const int bh = blockIdx.y;
    const int b  = bh >> 4;
    const int h  = bh & 15;
    const int q0 = blockIdx.x * 128;

    const float qscale = 0.125f * LOG2E;

    const float* qbase = Q + ((size_t)(b * SS + q0)) * HD + h * DD;
    #pragma unroll
    for (int l = 0; l < 8; l++) {
        const int idx = l * 256 + tid;
        const int r = idx >> 4, c4 = idx & 15;
        const float4 v4 = *(const float4*)(qbase + (size_t)r * HD + c4 * 4);
        float* d = Ps + r * ATS + c4 * 4;
        d[0] = tf32r(v4.x * qscale); d[1] = tf32r(v4.y * qscale);
        d[2] = tf32r(v4.z * qscale); d[3] = tf32r(v4.w * qscale);
    }
    __syncthreads();

    uint32_t qf[8][4];
    #pragma unroll
    for (int kk = 0; kk < 8; kk++) {
        const int base = (rb + g) * ATS + kk * 8 + t;
        qf[kk][0] = __float_as_uint(Ps[base]);
        qf[kk][1] = __float_as_uint(Ps[base + 8 * ATS]);
        qf[kk][2] = __float_as_uint(Ps[base + 4]);
        qf[kk][3] = __float_as_uint(Ps[base + 8 * ATS + 4]);
    }

    float acc[8][4];
    #pragma unroll
    for (int nt = 0; nt < 8; nt++)
        #pragma unroll
        for (int e = 0; e < 4; e++) acc[nt][e] = 0.f;
    float m0 = -1e30f, m1 = -1e30f, l0 = 0.f, l1 = 0.f;

    const float* kbase = Kg + ((size_t)b * SS) * HD + h * DD;
    const float* vbase = Vg + ((size_t)b * SS) * HD + h * DD;

    for (int kt = 0; kt < SS; kt += 64) {
        __syncthreads();
        #pragma unroll
        for (int l = 0; l < 4; l++) {
            const int idx = l * 256 + tid;
            const int r = idx >> 4, c4 = idx & 15;
            const float4 k4 = *(const float4*)(kbase + (size_t)(kt + r) * HD + c4 * 4);
            float* d = Ks + r * ATS + c4 * 4;
            d[0] = tf32r(k4.x); d[1] = tf32r(k4.y); d[2] = tf32r(k4.z); d[3] = tf32r(k4.w);
            const float4 v4 = *(const float4*)(vbase + (size_t)(kt + r) * HD + c4 * 4);
            Vt[(c4 * 4 + 0) * ATS + r] = tf32r(v4.x);
            Vt[(c4 * 4 + 1) * ATS + r] = tf32r(v4.y);
            Vt[(c4 * 4 + 2) * ATS + r] = tf32r(v4.z);
            Vt[(c4 * 4 + 3) * ATS + r] = tf32r(v4.w);
        }
        __syncthreads();

        float s[8][4];
        #pragma unroll
        for (int nt = 0; nt < 8; nt++)
            #pragma unroll
            for (int e = 0; e < 4; e++) s[nt][e] = 0.f;
        #pragma unroll
        for (int kk = 0; kk < 8; kk++) {
            uint32_t bf[8][2];
            #pragma unroll
            for (int nt = 0; nt < 8; nt++) {
                const int base = (nt * 8 + g) * ATS + kk * 8 + t;
                bf[nt][0] = __float_as_uint(Ks[base]);
                bf[nt][1] = __float_as_uint(Ks[base + 4]);
            }
            #pragma unroll
            for (int nt = 0; nt < 8; nt++)
                mma_tf32_16x8x8(s[nt], qf[kk], bf[nt]);
        }

        float rm0 = s[0][0], rm1 = s[0][2];
        #pragma unroll
        for (int nt = 0; nt < 8; nt++) {
            rm0 = fmaxf(rm0, fmaxf(s[nt][0], s[nt][1]));
            rm1 = fmaxf(rm1, fmaxf(s[nt][2], s[nt][3]));
        }
        rm0 = fmaxf(rm0, __shfl_xor_sync(0xffffffffu, rm0, 1));
        rm0 = fmaxf(rm0, __shfl_xor_sync(0xffffffffu, rm0, 2));
        rm1 = fmaxf(rm1, __shfl_xor_sync(0xffffffffu, rm1, 1));
        rm1 = fmaxf(rm1, __shfl_xor_sync(0xffffffffu, rm1, 2));
        const float mt0 = fmaxf(m0, rm0);
        const float mt1 = fmaxf(m1, rm1);
        if (mt0 > m0) {
            const float c0 = fexp2(m0 - mt0);
            l0 *= c0;
            #pragma unroll
            for (int nt = 0; nt < 8; nt++) { acc[nt][0] *= c0; acc[nt][1] *= c0; }
            m0 = mt0;
        }
        if (mt1 > m1) {
            const float c1 = fexp2(m1 - mt1);
            l1 *= c1;
            #pragma unroll
            for (int nt = 0; nt < 8; nt++) { acc[nt][2] *= c1; acc[nt][3] *= c1; }
            m1 = mt1;
        }

        float ps0 = 0.f, ps1 = 0.f;
        #pragma unroll
        for (int nt = 0; nt < 8; nt++) {
            const float p00 = tf32r(fexp2(s[nt][0] - m0));
            const float p01 = tf32r(fexp2(s[nt][1] - m0));
            const float p10 = tf32r(fexp2(s[nt][2] - m1));
            const float p11 = tf32r(fexp2(s[nt][3] - m1));
            ps0 += p00 + p01;
            ps1 += p10 + p11;
            *(float2*)&Ps[(rb + g) * ATS + nt * 8 + 2 * t]     = make_float2(p00, p01);
            *(float2*)&Ps[(rb + g + 8) * ATS + nt * 8 + 2 * t] = make_float2(p10, p11);
        }
        ps0 += __shfl_xor_sync(0xffffffffu, ps0, 1);
        ps0 += __shfl_xor_sync(0xffffffffu, ps0, 2);
        ps1 += __shfl_xor_sync(0xffffffffu, ps1, 1);
        ps1 += __shfl_xor_sync(0xffffffffu, ps1, 2);
        l0 += ps0;
        l1 += ps1;
        __syncwarp();

        #pragma unroll
        for (int kk = 0; kk < 8; kk++) {
            uint32_t af[4];
            const int base = (rb + g) * ATS + kk * 8 + t;
            af[0] = __float_as_uint(Ps[base]);
            af[1] = __float_as_uint(Ps[base + 8 * ATS]);
            af[2] = __float_as_uint(Ps[base + 4]);
            af[3] = __float_as_uint(Ps[base + 8 * ATS + 4]);
            #pragma unroll
            for (int nt = 0; nt < 8; nt++) {
                uint32_t bf[2];
                const int vb = (nt * 8 + g) * ATS + kk * 8 + t;
                bf[0] = __float_as_uint(Vt[vb]);
                bf[1] = __float_as_uint(Vt[vb + 4]);
                mma_tf32_16x8x8(acc[nt], af, bf);
            }
        }
    }

    const float i0 = 1.f / l0;
    const float i1 = 1.f / l1;
    const int r0 = q0 + rb + g;
    const int r1 = r0 + 8;
    float* o0 = O + ((size_t)(b * SS + r0)) * HD + h * DD;
    float* o1 = O + ((size_t)(b * SS + r1)) * HD + h * DD;
    #pragma unroll
    for (int nt = 0; nt < 8; nt++) {
        *(float2*)(o0 + nt * 8 + 2 * t) = make_float2(acc[nt][0] * i0, acc[nt][1] * i0);
        *(float2*)(o1 + nt * 8 + 2 * t) = make_float2(acc[nt][2] * i1, acc[nt][3] * i1);
    }
}

// ---------------- LayerNorm over last dim (1024), eps=1e-12 ----------------
__global__ __launch_bounds__(256)
void ln_kernel(const float* __restrict__ in, const float* __restrict__ gamma,
               const float* __restrict__ beta, float* __restrict__ out)
{
    const int row = blockIdx.x;
    const int tid = threadIdx.x;
    const float4 xv = ((const float4*)(in + (size_t)row * HD))[tid];

    __shared__ float red[32];
    float s = xv.x + xv.y + xv.z + xv.w;
    #pragma unroll
    for (int o = 16; o > 0; o >>= 1) s += __shfl_xor_sync(0xffffffffu, s, o);
    if ((tid & 31) == 0) red[tid >> 5] = s;
    __syncthreads();
    if (tid < 32) {
        float t = (tid < 8) ? red[tid] : 0.f;
        #pragma unroll
        for (int o = 4; o > 0; o >>= 1) t += __shfl_xor_sync(0xffffffffu, t, o);
        if (tid == 0) red[0] = t;
    }
    __syncthreads();
    const float mu = red[0] * (1.f / 1024.f);
    __syncthreads();

    const float dx = xv.x - mu, dy = xv.y - mu, dz = xv.z - mu, dw = xv.w - mu;
    float sq = dx*dx + dy*dy + dz*dz + dw*dw;
    #pragma unroll
    for (int o = 16; o > 0; o >>= 1) sq += __shfl_xor_sync(0xffffffffu, sq, o);
    if ((tid & 31) == 0) red[tid >> 5] = sq;
    __syncthreads();
    if (tid < 32) {
        float t = (tid < 8) ? red[tid] : 0.f;
        #pragma unroll
        for (int o = 4; o > 0; o >>= 1) t += __shfl_xor_sync(0xffffffffu, t, o);
        if (tid == 0) red[0] = t;
    }
    __syncthreads();
    const float var  = red[0] * (1.f / 1024.f);
    const float rstd = rsqrtf(var + 1e-12f);

    const float4 gv = ((const float4*)gamma)[tid];
    const float4 bv = ((const float4*)beta )[tid];
    float4 ov;
    ov.x = dx * rstd * gv.x + bv.x;
    ov.y = dy * rstd * gv.y + bv.y;
    ov.z = dz * rstd * gv.z + bv.z;
    ov.w = dw * rstd * gv.w + bv.w;
    ((float4*)(out + (size_t)row * HD))[tid] = ov;
}

// ---------------- launch ----------------------------------------------------
extern "C" void kernel_launch(void* const* d_in, const int* in_sizes, int n_in,
                              void* d_out, int out_size)
{
    const float* x     = (const float*)d_in[0];
    const float* Wq    = (const float*)d_in[1];
    const float* bq    = (const float*)d_in[2];
    const float* Wk    = (const float*)d_in[3];
    const float* bk    = (const float*)d_in[4];
    const float* Wv    = (const float*)d_in[5];
    const float* bv    = (const float*)d_in[6];
    const float* Wo    = (const float*)d_in[7];
    const float* bo    = (const float*)d_in[8];
    const float* g1    = (const float*)d_in[9];
    const float* beta1 = (const float*)d_in[10];
    const float* W1    = (const float*)d_in[11];
    const float* b1    = (const float*)d_in[12];
    const float* W2    = (const float*)d_in[13];
    const float* b2    = (const float*)d_in[14];
    const float* g2    = (const float*)d_in[15];
    const float* beta2 = (const float*)d_in[16];
    float* out = (float*)d_out;

    float *q, *k, *v, *ctx, *r1, *h, *ff, *r2;
    float *wqkvt, *bqkv, *wot, *w1t, *w2t;
    cudaGetSymbolAddress((void**)&q,     g_q);
    cudaGetSymbolAddress((void**)&k,     g_k);
    cudaGetSymbolAddress((void**)&v,     g_v);
    cudaGetSymbolAddress((void**)&ctx,   g_ctx);
    cudaGetSymbolAddress((void**)&r1,    g_r1);
    cudaGetSymbolAddress((void**)&h,     g_h);
    cudaGetSymbolAddress((void**)&ff,    g_ff);
    cudaGetSymbolAddress((void**)&r2,    g_r2);
    cudaGetSymbolAddress((void**)&wqkvt, g_wqkvt);
    cudaGetSymbolAddress((void**)&bqkv,  g_bqkv);
    cudaGetSymbolAddress((void**)&wot,   g_wot);
    cudaGetSymbolAddress((void**)&w1t,   g_w1t);
    cudaGetSymbolAddress((void**)&w2t,   g_w2t);

    const int GEMM_SMEM = 4 * GBUF * 4;   // 73728 B
    const int ATT_SMEM  = 256 * ATS * 4;  // 69632 B
    cudaFuncSetAttribute(gemm_mma<0>, cudaFuncAttributeMaxDynamicSharedMemorySize, GEMM_SMEM);
    cudaFuncSetAttribute(gemm_mma<1>, cudaFuncAttributeMaxDynamicSharedMemorySize, GEMM_SMEM);
    cudaFuncSetAttribute(gemm_mma<2>, cudaFuncAttributeMaxDynamicSharedMemorySize, GEMM_SMEM);
    cudaFuncSetAttribute(attn_mma, cudaFuncAttributeMaxDynamicSharedMemorySize, ATT_SMEM);

    // tables + packed transposed weights
    rope_tab_kernel<<<SS, 32>>>();
    pack_bias_kernel<<<(3 * HD + 255) / 256, 256>>>(bq, bk, bv);
    const dim3 tb(32, 8);
    transpose_rna<<<dim3(HD / 32,  HD / 32),  tb>>>(Wq, wqkvt,              HD,  HD);
    transpose_rna<<<dim3(HD / 32,  HD / 32),  tb>>>(Wk, wqkvt + HD * HD,    HD,  HD);
    transpose_rna<<<dim3(HD / 32,  HD / 32),  tb>>>(Wv, wqkvt + 2 * HD * HD, HD, HD);
    transpose_rna<<<dim3(HD / 32,  HD / 32),  tb>>>(Wo, wot, HD,  HD);
    transpose_rna<<<dim3(FFD / 32, HD / 32),  tb>>>(W1, w1t, HD,  FFD);
    transpose_rna<<<dim3(HD / 32,  FFD / 32), tb>>>(W2, w2t, FFD, HD);

    const dim3 gQKV(3 * HD / 128, BSR / 128);  // (24, 64)
    const dim3 gHd (HD  / 128,    BSR / 128);  // (8, 64)
    const dim3 gFf (FFD / 128,    BSR / 128);  // (32, 64)

    // fused QKV projection + bias + RoPE
    gemm_mma<2><<<gQKV, 256, GEMM_SMEM>>>(x, wqkvt, bqkv, nullptr, q, BSR, HD, HD, k, v);

    // Flash attention on tensor cores -> ctx
    attn_mma<<<dim3(SS / 128, BB * NHH), 256, ATT_SMEM>>>(q, k, v, ctx);

    // O projection + residual(x) -> r1 ; LN -> h
    gemm_mma<0><<<gHd, 256, GEMM_SMEM>>>(ctx, wot, bo, x, r1, BSR, HD, HD);
    ln_kernel<<<BSR, 256>>>(r1, g1, beta1, h);

    // FFN
    gemm_mma<1><<<gFf, 256, GEMM_SMEM>>>(h,  w1t, b1, nullptr, ff, BSR, FFD, HD);
    gemm_mma<0><<<gHd, 256, GEMM_SMEM>>>(ff, w2t, b2, h,       r2, BSR, HD, FFD);

    // final LN -> out
    ln_kernel<<<BSR, 256>>>(r2, g2, beta2, out);
}

// round 9
// speedup vs baseline: 4.0308x; 1.0631x over previous
#include <cuda_runtime.h>
#include <cuda_bf16.h>
#include <math.h>
#include <stdint.h>

// Problem constants
#define BB   4
#define SS   2048
#define HD   1024
#define NHH  16
#define DD   64
#define FFD  4096
#define BSR  (BB*SS)          // 8192 rows
#define LOG2E 1.4426950408889634f

// ---------------- scratch (device globals: no allocation allowed) ----------
__device__ float g_q  [BSR * HD];
__device__ float g_k  [BSR * HD];
__device__ float g_v  [BSR * HD];
__device__ float g_ctx[BSR * HD];
__device__ float g_r1 [BSR * HD];
__device__ float g_h  [BSR * HD];
__device__ float g_ff [BSR * FFD];
__device__ float g_r2 [BSR * HD];
// packed transposed (N,K) tf32-rounded weights
__device__ float g_wqkvt[3 * HD * HD];
__device__ float g_bqkv [3 * HD];
__device__ float g_wot[HD * HD];
__device__ float g_w1t[FFD * HD];
__device__ float g_w2t[HD * FFD];
// rope cos/sin table [S][32]
__device__ float2 g_ropetab[SS * 32];

__device__ __forceinline__ float tf32r(float x) {
    float r;
    asm("cvt.rna.tf32.f32 %0, %1;" : "=f"(r) : "f"(x));
    return r;
}
__device__ __forceinline__ float tanh_fast(float x) {
    float y;
    asm("tanh.approx.f32 %0, %1;" : "=f"(y) : "f"(x));
    return y;
}
__device__ __forceinline__ uint32_t smem_u32(const void* p) {
    uint32_t a;
    asm("{ .reg .u64 t; cvta.to.shared.u64 t, %1; cvt.u32.u64 %0, t; }" : "=r"(a) : "l"(p));
    return a;
}
__device__ __forceinline__ void cp_async16(uint32_t saddr, const void* g) {
    asm volatile("cp.async.cg.shared.global [%0], [%1], 16;" :: "r"(saddr), "l"(g));
}
__device__ __forceinline__ void cp_commit() {
    asm volatile("cp.async.commit_group;" ::: "memory");
}
template<int N> __device__ __forceinline__ void cp_wait() {
    asm volatile("cp.async.wait_group %0;" :: "n"(N) : "memory");
}

// fast exp2 on the fma/alu pipes (valid for x <= ~0; clamps at -126)
__device__ __forceinline__ float fexp2(float x) {
    x = fmaxf(x, -126.f);
    const float k = x + 12582912.f;
    const int   ik = __float_as_int(k) - 0x4B400000;
    const float f = x - (k - 12582912.f);
    float p = 9.6181291e-3f;
    p = fmaf(p, f, 5.5504109e-2f);
    p = fmaf(p, f, 2.4022651e-1f);
    p = fmaf(p, f, 6.9314718e-1f);
    p = fmaf(p, f, 1.0f);
    return __int_as_float(__float_as_int(p) + (ik << 23));
}

__device__ __forceinline__ void mma_tf32_16x8x8(float* c, const uint32_t* a, const uint32_t* b) {
    asm volatile(
        "mma.sync.aligned.m16n8k8.row.col.f32.tf32.tf32.f32 "
        "{%0,%1,%2,%3}, {%4,%5,%6,%7}, {%8,%9}, {%0,%1,%2,%3};"
        : "+f"(c[0]), "+f"(c[1]), "+f"(c[2]), "+f"(c[3])
        : "r"(a[0]), "r"(a[1]), "r"(a[2]), "r"(a[3]), "r"(b[0]), "r"(b[1]));
}

// =================== tf32 mma.sync GEMM (3-stage cp.async) =================
// EPI: 0 = bias(+add), 1 = bias+gelu, 2 = fused QKV + RoPE
// BM=BN=128, BK=32, 256 threads (8 warps), warp tile 64x32.
// 3 smem stages, ONE __syncthreads per K-iteration:
//   copy for stage it+2 targets buffer (it+2)%3 == (it-1)%3, whose readers
//   all passed this iteration's barrier already.
#define AST 36
#define GBUF (128 * AST)

__device__ __forceinline__ void stage_copy(const float* __restrict__ A,
                                           const float* __restrict__ Bt,
                                           int K, int crow, int ccol, int k0,
                                           float* sa, float* sb, int tid)
{
    const int r0 = tid >> 3;
    const int c  = (tid & 7) * 4;
    #pragma unroll
    for (int i = 0; i < 4; i++) {
        const int row = i * 32 + r0;
        cp_async16(smem_u32(sa + row * AST + c), A  + (size_t)(crow + row) * K + k0 + c);
        cp_async16(smem_u32(sb + row * AST + c), Bt + (size_t)(ccol + row) * K + k0 + c);
    }
}

template<int EPI>
__global__ __launch_bounds__(256, 2)
void gemm_mma(const float* __restrict__ A, const float* __restrict__ Bt,
              const float* __restrict__ bias, const float* __restrict__ add,
              float* __restrict__ C, int M, int N, int K,
              float* __restrict__ Ck = nullptr, float* __restrict__ Cv = nullptr)
{
    extern __shared__ float smem[];
    float* As = smem;              // [3][GBUF]
    float* Bs = smem + 3 * GBUF;   // [3][GBUF]

    const int tid  = threadIdx.x;
    const int wid  = tid >> 5;
    const int lane = tid & 31;
    const int g    = lane >> 2;
    const int t    = lane & 3;

    const int crow = blockIdx.y * 128;
    const int ccol = blockIdx.x * 128;

    const int rb = (wid & 1) * 64;
    const int cb = (wid >> 1) * 32;

    float acc[4][4][4];
    #pragma unroll
    for (int i = 0; i < 4; i++)
        #pragma unroll
        for (int j = 0; j < 4; j++)
            #pragma unroll
            for (int e = 0; e < 4; e++) acc[i][j][e] = 0.f;

    const int niter = K >> 5;

    stage_copy(A, Bt, K, crow, ccol, 0,  As,        Bs,        tid);
    cp_commit();
    stage_copy(A, Bt, K, crow, ccol, 32, As + GBUF, Bs + GBUF, tid);
    cp_commit();

    int buf = 0;                   // it % 3
    for (int it = 0; it < niter; ++it) {
        cp_wait<1>();
        __syncthreads();           // stage it ready; all warps done with stage it-1

        // issue copy for stage it+2 into buffer (it+2)%3 (freed at it-1)
        const int nbuf = (buf + 2 >= 3) ? buf - 1 : buf + 2;
        if (it + 2 < niter)
            stage_copy(A, Bt, K, crow, ccol, (it + 2) << 5,
                       As + nbuf * GBUF, Bs + nbuf * GBUF, tid);
        cp_commit();               // always commit: uniform group accounting

        const float* as = As + buf * GBUF;
        const float* bs = Bs + buf * GBUF;
        #pragma unroll
        for (int kk = 0; kk < 32; kk += 8) {
            uint32_t af[4][4], bf[4][2];
            #pragma unroll
            for (int mt = 0; mt < 4; mt++) {
                const int base = (rb + mt * 16 + g) * AST + kk + t;
                af[mt][0] = __float_as_uint(as[base]);
                af[mt][1] = __float_as_uint(as[base + 8 * AST]);
                af[mt][2] = __float_as_uint(as[base + 4]);
                af[mt][3] = __float_as_uint(as[base + 8 * AST + 4]);
            }
            #pragma unroll
            for (int nt = 0; nt < 4; nt++) {
                const int base = (cb + nt * 8 + g) * AST + kk + t;
                bf[nt][0] = __float_as_uint(bs[base]);
                bf[nt][1] = __float_as_uint(bs[base + 4]);
            }
            #pragma unroll
            for (int mt = 0; mt < 4; mt++)
                #pragma unroll
                for (int nt = 0; nt < 4; nt++)
                    mma_tf32_16x8x8(acc[mt][nt], af[mt], bf[nt]);
        }

        buf = (buf + 1 >= 3) ? 0 : buf + 1;
    }

    // -------- epilogue --------
    float* Cout = C;
    int colmask = ~0;
    bool dorope = false;
    if (EPI == 2) {
        const int sel = ccol >> 10;
        Cout = (sel == 0) ? C : (sel == 1 ? Ck : Cv);
        colmask = 1023;
        dorope = (sel < 2);
    }

    #pragma unroll
    for (int mt = 0; mt < 4; mt++) {
        #pragma unroll
        for (int half = 0; half < 2; half++) {
            const int r = crow + rb + mt * 16 + g + half * 8;
            const int s = r & (SS - 1);
            #pragma unroll
            for (int nt = 0; nt < 4; nt++) {
                const int cg = ccol + cb + nt * 8 + t * 2;
                float v0 = acc[mt][nt][half * 2 + 0] + bias[cg + 0];
                float v1 = acc[mt][nt][half * 2 + 1] + bias[cg + 1];
                if (EPI == 0 || EPI == 1) {
                    if (add) {
                        const float2 a2 = *(const float2*)(add + (size_t)r * N + cg);
                        v0 += a2.x; v1 += a2.y;
                    }
                    if (EPI == 1) {
                        const float t0 = tanh_fast(0.7978845608028654f * (v0 + 0.044715f * v0 * v0 * v0));
                        const float t1 = tanh_fast(0.7978845608028654f * (v1 + 0.044715f * v1 * v1 * v1));
                        v0 = 0.5f * v0 * (1.f + t0);
                        v1 = 0.5f * v1 * (1.f + t1);
                    }
                    *(float2*)(C + (size_t)r * N + cg) = make_float2(v0, v1);
                } else {
                    const int cl = cg & colmask;
                    if (dorope) {
                        const int i = (cl & 63) >> 1;
                        const float2 cs = g_ropetab[s * 32 + i];
                        const float n0 = v0 * cs.x - v1 * cs.y;
                        const float n1 = v1 * cs.x + v0 * cs.y;
                        v0 = n0; v1 = n1;
                    }
                    *(float2*)(Cout + (size_t)r * HD + cl) = make_float2(v0, v1);
                }
            }
        }
    }
}

// ------------- weight transpose + tf32 rounding: in[R,C] -> out[C,R] -------
__global__ __launch_bounds__(256)
void transpose_rna(const float* __restrict__ in, float* __restrict__ out, int R, int C)
{
    __shared__ float t[32][33];
    const int bx = blockIdx.x * 32, by = blockIdx.y * 32;
    const int tx = threadIdx.x, ty = threadIdx.y;
    #pragma unroll
    for (int i = 0; i < 32; i += 8)
        t[ty + i][tx] = in[(size_t)(by + ty + i) * C + bx + tx];
    __syncthreads();
    #pragma unroll
    for (int i = 0; i < 32; i += 8)
        out[(size_t)(bx + ty + i) * R + by + tx] = tf32r(t[tx][ty + i]);
}

// ---------------- rope table + bias pack -----------------------------------
__global__ void rope_tab_kernel() {
    const int s = blockIdx.x;
    const int i = threadIdx.x;
    const float inv = (float)pow(10000.0, -((double)(2 * i)) / 64.0);
    float sn, c;
    sincosf((float)s * inv, &sn, &c);
    g_ropetab[s * 32 + i] = make_float2(c, sn);
}
__global__ void pack_bias_kernel(const float* bq, const float* bk, const float* bv) {
    const int i = blockIdx.x * blockDim.x + threadIdx.x;
    if (i < HD)           g_bqkv[i] = bq[i];
    else if (i < 2 * HD)  g_bqkv[i] = bk[i - HD];
    else if (i < 3 * HD)  g_bqkv[i] = bv[i - 2 * HD];
}

// ============== Flash attention on tensor cores (tf32 mma.sync) ============
#define ATS 68
__global__ __launch_bounds__(256)
void attn_mma(const float* __restrict__ Q, const float* __restrict__ Kg,
              const float* __restrict__ Vg, float* __restrict__ O)
{
    extern __shared__ float sm[];
    float* Ks = sm;
    float* Vt = sm + 64 * ATS;
    float* Ps = sm + 128 * ATS;

    const int tid  = threadIdx.x;
    const int wid  = tid >> 5;
    const int lane = tid & 31;
    const int g    = lane >> 2;
    const int t    = lane & 3;
    const int rb   = wid * 16;

    const int bh = blockIdx.y;
    const int b  = bh >> 4;
    const int h  = bh & 15;
    const int q0 = blockIdx.x * 128;

    const float qscale = 0.125f * LOG2E;

    const float* qbase = Q + ((size_t)(b * SS + q0)) * HD + h * DD;
    #pragma unroll
    for (int l = 0; l < 8; l++) {
        const int idx = l * 256 + tid;
        const int r = idx >> 4, c4 = idx & 15;
        const float4 v4 = *(const float4*)(qbase + (size_t)r * HD + c4 * 4);
        float* d = Ps + r * ATS + c4 * 4;
        d[0] = tf32r(v4.x * qscale); d[1] = tf32r(v4.y * qscale);
        d[2] = tf32r(v4.z * qscale); d[3] = tf32r(v4.w * qscale);
    }
    __syncthreads();

    uint32_t qf[8][4];
    #pragma unroll
    for (int kk = 0; kk < 8; kk++) {
        const int base = (rb + g) * ATS + kk * 8 + t;
        qf[kk][0] = __float_as_uint(Ps[base]);
        qf[kk][1] = __float_as_uint(Ps[base + 8 * ATS]);
        qf[kk][2] = __float_as_uint(Ps[base + 4]);
        qf[kk][3] = __float_as_uint(Ps[base + 8 * ATS + 4]);
    }

    float acc[8][4];
    #pragma unroll
    for (int nt = 0; nt < 8; nt++)
        #pragma unroll
        for (int e = 0; e < 4; e++) acc[nt][e] = 0.f;
    float m0 = -1e30f, m1 = -1e30f, l0 = 0.f, l1 = 0.f;

    const float* kbase = Kg + ((size_t)b * SS) * HD + h * DD;
    const float* vbase = Vg + ((size_t)b * SS) * HD + h * DD;

    for (int kt = 0; kt < SS; kt += 64) {
        __syncthreads();
        #pragma unroll
        for (int l = 0; l < 4; l++) {
            const int idx = l * 256 + tid;
            const int r = idx >> 4, c4 = idx & 15;
            const float4 k4 = *(const float4*)(kbase + (size_t)(kt + r) * HD + c4 * 4);
            float* d = Ks + r * ATS + c4 * 4;
            d[0] = tf32r(k4.x); d[1] = tf32r(k4.y); d[2] = tf32r(k4.z); d[3] = tf32r(k4.w);
            const float4 v4 = *(const float4*)(vbase + (size_t)(kt + r) * HD + c4 * 4);
            Vt[(c4 * 4 + 0) * ATS + r] = tf32r(v4.x);
            Vt[(c4 * 4 + 1) * ATS + r] = tf32r(v4.y);
            Vt[(c4 * 4 + 2) * ATS + r] = tf32r(v4.z);
            Vt[(c4 * 4 + 3) * ATS + r] = tf32r(v4.w);
        }
        __syncthreads();

        float s[8][4];
        #pragma unroll
        for (int nt = 0; nt < 8; nt++)
            #pragma unroll
            for (int e = 0; e < 4; e++) s[nt][e] = 0.f;
        #pragma unroll
        for (int kk = 0; kk < 8; kk++) {
            uint32_t bf[8][2];
            #pragma unroll
            for (int nt = 0; nt < 8; nt++) {
                const int base = (nt * 8 + g) * ATS + kk * 8 + t;
                bf[nt][0] = __float_as_uint(Ks[base]);
                bf[nt][1] = __float_as_uint(Ks[base + 4]);
            }
            #pragma unroll
            for (int nt = 0; nt < 8; nt++)
                mma_tf32_16x8x8(s[nt], qf[kk], bf[nt]);
        }

        float rm0 = s[0][0], rm1 = s[0][2];
        #pragma unroll
        for (int nt = 0; nt < 8; nt++) {
            rm0 = fmaxf(rm0, fmaxf(s[nt][0], s[nt][1]));
            rm1 = fmaxf(rm1, fmaxf(s[nt][2], s[nt][3]));
        }
        rm0 = fmaxf(rm0, __shfl_xor_sync(0xffffffffu, rm0, 1));
        rm0 = fmaxf(rm0, __shfl_xor_sync(0xffffffffu, rm0, 2));
        rm1 = fmaxf(rm1, __shfl_xor_sync(0xffffffffu, rm1, 1));
        rm1 = fmaxf(rm1, __shfl_xor_sync(0xffffffffu, rm1, 2));
        const float mt0 = fmaxf(m0, rm0);
        const float mt1 = fmaxf(m1, rm1);
        if (mt0 > m0) {
            const float c0 = fexp2(m0 - mt0);
            l0 *= c0;
            #pragma unroll
            for (int nt = 0; nt < 8; nt++) { acc[nt][0] *= c0; acc[nt][1] *= c0; }
            m0 = mt0;
        }
        if (mt1 > m1) {
            const float c1 = fexp2(m1 - mt1);
            l1 *= c1;
            #pragma unroll
            for (int nt = 0; nt < 8; nt++) { acc[nt][2] *= c1; acc[nt][3] *= c1; }
            m1 = mt1;
        }

        float ps0 = 0.f, ps1 = 0.f;
        #pragma unroll
        for (int nt = 0; nt < 8; nt++) {
            const float p00 = tf32r(fexp2(s[nt][0] - m0));
            const float p01 = tf32r(fexp2(s[nt][1] - m0));
            const float p10 = tf32r(fexp2(s[nt][2] - m1));
            const float p11 = tf32r(fexp2(s[nt][3] - m1));
            ps0 += p00 + p01;
            ps1 += p10 + p11;
            *(float2*)&Ps[(rb + g) * ATS + nt * 8 + 2 * t]     = make_float2(p00, p01);
            *(float2*)&Ps[(rb + g + 8) * ATS + nt * 8 + 2 * t] = make_float2(p10, p11);
        }
        ps0 += __shfl_xor_sync(0xffffffffu, ps0, 1);
        ps0 += __shfl_xor_sync(0xffffffffu, ps0, 2);
        ps1 += __shfl_xor_sync(0xffffffffu, ps1, 1);
        ps1 += __shfl_xor_sync(0xffffffffu, ps1, 2);
        l0 += ps0;
        l1 += ps1;
        __syncwarp();

        #pragma unroll
        for (int kk = 0; kk < 8; kk++) {
            uint32_t af[4];
            const int base = (rb + g) * ATS + kk * 8 + t;
            af[0] = __float_as_uint(Ps[base]);
            af[1] = __float_as_uint(Ps[base + 8 * ATS]);
            af[2] = __float_as_uint(Ps[base + 4]);
            af[3] = __float_as_uint(Ps[base + 8 * ATS + 4]);
            #pragma unroll
            for (int nt = 0; nt < 8; nt++) {
                uint32_t bf[2];
                const int vb = (nt * 8 + g) * ATS + kk * 8 + t;
                bf[0] = __float_as_uint(Vt[vb]);
                bf[1] = __float_as_uint(Vt[vb + 4]);
                mma_tf32_16x8x8(acc[nt], af, bf);
            }
        }
    }

    const float i0 = 1.f / l0;
    const float i1 = 1.f / l1;
    const int r0 = q0 + rb + g;
    const int r1 = r0 + 8;
    float* o0 = O + ((size_t)(b * SS + r0)) * HD + h * DD;
    float* o1 = O + ((size_t)(b * SS + r1)) * HD + h * DD;
    #pragma unroll
    for (int nt = 0; nt < 8; nt++) {
        *(float2*)(o0 + nt * 8 + 2 * t) = make_float2(acc[nt][0] * i0, acc[nt][1] * i0);
        *(float2*)(o1 + nt * 8 + 2 * t) = make_float2(acc[nt][2] * i1, acc[nt][3] * i1);
    }
}

// ---------------- LayerNorm over last dim (1024), eps=1e-12 ----------------
__global__ __launch_bounds__(256)
void ln_kernel(const float* __restrict__ in, const float* __restrict__ gamma,
               const float* __restrict__ beta, float* __restrict__ out)
{
    const int row = blockIdx.x;
    const int tid = threadIdx.x;
    const float4 xv = ((const float4*)(in + (size_t)row * HD))[tid];

    __shared__ float red[32];
    float s = xv.x + xv.y + xv.z + xv.w;
    #pragma unroll
    for (int o = 16; o > 0; o >>= 1) s += __shfl_xor_sync(0xffffffffu, s, o);
    if ((tid & 31) == 0) red[tid >> 5] = s;
    __syncthreads();
    if (tid < 32) {
        float t = (tid < 8) ? red[tid] : 0.f;
        #pragma unroll
        for (int o = 4; o > 0; o >>= 1) t += __shfl_xor_sync(0xffffffffu, t, o);
        if (tid == 0) red[0] = t;
    }
    __syncthreads();
    const float mu = red[0] * (1.f / 1024.f);
    __syncthreads();

    const float dx = xv.x - mu, dy = xv.y - mu, dz = xv.z - mu, dw = xv.w - mu;
    float sq = dx*dx + dy*dy + dz*dz + dw*dw;
    #pragma unroll
    for (int o = 16; o > 0; o >>= 1) sq += __shfl_xor_sync(0xffffffffu, sq, o);
    if ((tid & 31) == 0) red[tid >> 5] = sq;
    __syncthreads();
    if (tid < 32) {
        float t = (tid < 8) ? red[tid] : 0.f;
        #pragma unroll
        for (int o = 4; o > 0; o >>= 1) t += __shfl_xor_sync(0xffffffffu, t, o);
        if (tid == 0) red[0] = t;
    }
    __syncthreads();
    const float var  = red[0] * (1.f / 1024.f);
    const float rstd = rsqrtf(var + 1e-12f);

    const float4 gv = ((const float4*)gamma)[tid];
    const float4 bv = ((const float4*)beta )[tid];
    float4 ov;
    ov.x = dx * rstd * gv.x + bv.x;
    ov.y = dy * rstd * gv.y + bv.y;
    ov.z = dz * rstd * gv.z + bv.z;
    ov.w = dw * rstd * gv.w + bv.w;
    ((float4*)(out + (size_t)row * HD))[tid] = ov;
}

// ---------------- launch ----------------------------------------------------
extern "C" void kernel_launch(void* const* d_in, const int* in_sizes, int n_in,
                              void* d_out, int out_size)
{
    const float* x     = (const float*)d_in[0];
    const float* Wq    = (const float*)d_in[1];
    const float* bq    = (const float*)d_in[2];
    const float* Wk    = (const float*)d_in[3];
    const float* bk    = (const float*)d_in[4];
    const float* Wv    = (const float*)d_in[5];
    const float* bv    = (const float*)d_in[6];
    const float* Wo    = (const float*)d_in[7];
    const float* bo    = (const float*)d_in[8];
    const float* g1    = (const float*)d_in[9];
    const float* beta1 = (const float*)d_in[10];
    const float* W1    = (const float*)d_in[11];
    const float* b1    = (const float*)d_in[12];
    const float* W2    = (const float*)d_in[13];
    const float* b2    = (const float*)d_in[14];
    const float* g2    = (const float*)d_in[15];
    const float* beta2 = (const float*)d_in[16];
    float* out = (float*)d_out;

    float *q, *k, *v, *ctx, *r1, *h, *ff, *r2;
    float *wqkvt, *bqkv, *wot, *w1t, *w2t;
    cudaGetSymbolAddress((void**)&q,     g_q);
    cudaGetSymbolAddress((void**)&k,     g_k);
    cudaGetSymbolAddress((void**)&v,     g_v);
    cudaGetSymbolAddress((void**)&ctx,   g_ctx);
    cudaGetSymbolAddress((void**)&r1,    g_r1);
    cudaGetSymbolAddress((void**)&h,     g_h);
    cudaGetSymbolAddress((void**)&ff,    g_ff);
    cudaGetSymbolAddress((void**)&r2,    g_r2);
    cudaGetSymbolAddress((void**)&wqkvt, g_wqkvt);
    cudaGetSymbolAddress((void**)&bqkv,  g_bqkv);
    cudaGetSymbolAddress((void**)&wot,   g_wot);
    cudaGetSymbolAddress((void**)&w1t,   g_w1t);
    cudaGetSymbolAddress((void**)&w2t,   g_w2t);

    const int GEMM_SMEM = 6 * GBUF * 4;   // 110592 B (3 stages x 2 operands)
    const int ATT_SMEM  = 256 * ATS * 4;  // 69632 B
    cudaFuncSetAttribute(gemm_mma<0>, cudaFuncAttributeMaxDynamicSharedMemorySize, GEMM_SMEM);
    cudaFuncSetAttribute(gemm_mma<1>, cudaFuncAttributeMaxDynamicSharedMemorySize, GEMM_SMEM);
    cudaFuncSetAttribute(gemm_mma<2>, cudaFuncAttributeMaxDynamicSharedMemorySize, GEMM_SMEM);
    cudaFuncSetAttribute(attn_mma, cudaFuncAttributeMaxDynamicSharedMemorySize, ATT_SMEM);

    // tables + packed transposed weights
    rope_tab_kernel<<<SS, 32>>>();
    pack_bias_kernel<<<(3 * HD + 255) / 256, 256>>>(bq, bk, bv);
    const dim3 tb(32, 8);
    transpose_rna<<<dim3(HD / 32,  HD / 32),  tb>>>(Wq, wqkvt,               HD,  HD);
    transpose_rna<<<dim3(HD / 32,  HD / 32),  tb>>>(Wk, wqkvt + HD * HD,     HD,  HD);
    transpose_rna<<<dim3(HD / 32,  HD / 32),  tb>>>(Wv, wqkvt + 2 * HD * HD, HD,  HD);
    transpose_rna<<<dim3(HD / 32,  HD / 32),  tb>>>(Wo, wot, HD,  HD);
    transpose_rna<<<dim3(FFD / 32, HD / 32),  tb>>>(W1, w1t, HD,  FFD);
    transpose_rna<<<dim3(HD / 32,  FFD / 32), tb>>>(W2, w2t, FFD, HD);

    const dim3 gQKV(3 * HD / 128, BSR / 128);  // (24, 64)
    const dim3 gHd (HD  / 128,    BSR / 128);  // (8, 64)
    const dim3 gFf (FFD / 128,    BSR / 128);  // (32, 64)

    // fused QKV projection + bias + RoPE
    gemm_mma<2><<<gQKV, 256, GEMM_SMEM>>>(x, wqkvt, bqkv, nullptr, q, BSR, HD, HD, k, v);

    // Flash attention on tensor cores -> ctx
    attn_mma<<<dim3(SS / 128, BB * NHH), 256, ATT_SMEM>>>(q, k, v, ctx);

    // O projection + residual(x) -> r1 ; LN -> h
    gemm_mma<0><<<gHd, 256, GEMM_SMEM>>>(ctx, wot, bo, x, r1, BSR, HD, HD);
    ln_kernel<<<BSR, 256>>>(r1, g1, beta1, h);

    // FFN
    gemm_mma<1><<<gFf, 256, GEMM_SMEM>>>(h,  w1t, b1, nullptr, ff, BSR, FFD, HD);
    gemm_mma<0><<<gHd, 256, GEMM_SMEM>>>(ff, w2t, b2, h,       r2, BSR, HD, FFD);

    // final LN -> out
    ln_kernel<<<BSR, 256>>>(r2, g2, beta2, out);
}

// round 12
// speedup vs baseline: 4.2660x; 1.0584x over previous
#include <cuda_runtime.h>
#include <cuda_bf16.h>
#include <math.h>
#include <stdint.h>

// Problem constants
#define BB   4
#define SS   2048
#define HD   1024
#define NHH  16
#define DD   64
#define FFD  4096
#define BSR  (BB*SS)          // 8192 rows
#define LOG2E 1.4426950408889634f

// ---------------- scratch (device globals: no allocation allowed) ----------
__device__ float g_q  [BSR * HD];
__device__ float g_k  [BSR * HD];
__device__ float g_v  [BSR * HD];
__device__ float g_ctx[BSR * HD];
__device__ float g_r1 [BSR * HD];
__device__ float g_h  [BSR * HD];
__device__ float g_ff [BSR * FFD];
__device__ float g_r2 [BSR * HD];
// packed transposed (N,K) tf32-rounded weights
__device__ float g_wqkvt[3 * HD * HD];
__device__ float g_bqkv [3 * HD];
__device__ float g_wot[HD * HD];
__device__ float g_w1t[FFD * HD];
__device__ float g_w2t[HD * FFD];
// rope cos/sin table [S][32]
__device__ float2 g_ropetab[SS * 32];

__device__ __forceinline__ float tf32r(float x) {
    float r;
    asm("cvt.rna.tf32.f32 %0, %1;" : "=f"(r) : "f"(x));
    return r;
}
__device__ __forceinline__ float tanh_fast(float x) {
    float y;
    asm("tanh.approx.f32 %0, %1;" : "=f"(y) : "f"(x));
    return y;
}
__device__ __forceinline__ uint32_t smem_u32(const void* p) {
    uint32_t a;
    asm("{ .reg .u64 t; cvta.to.shared.u64 t, %1; cvt.u32.u64 %0, t; }" : "=r"(a) : "l"(p));
    return a;
}
__device__ __forceinline__ void cp_async16(uint32_t saddr, const void* g) {
    asm volatile("cp.async.cg.shared.global [%0], [%1], 16;" :: "r"(saddr), "l"(g));
}
__device__ __forceinline__ void cp_commit() {
    asm volatile("cp.async.commit_group;" ::: "memory");
}
template<int N> __device__ __forceinline__ void cp_wait() {
    asm volatile("cp.async.wait_group %0;" :: "n"(N) : "memory");
}

// fast exp2 on the fma/alu pipes (valid for x <= ~0; clamps at -126)
__device__ __forceinline__ float fexp2(float x) {
    x = fmaxf(x, -126.f);
    const float k = x + 12582912.f;
    const int   ik = __float_as_int(k) - 0x4B400000;
    const float f = x - (k - 12582912.f);
    float p = 9.6181291e-3f;
    p = fmaf(p, f, 5.5504109e-2f);
    p = fmaf(p, f, 2.4022651e-1f);
    p = fmaf(p, f, 6.9314718e-1f);
    p = fmaf(p, f, 1.0f);
    return __int_as_float(__float_as_int(p) + (ik << 23));
}

__device__ __forceinline__ void mma_tf32_16x8x8(float* c, const uint32_t* a, const uint32_t* b) {
    asm volatile(
        "mma.sync.aligned.m16n8k8.row.col.f32.tf32.tf32.f32 "
        "{%0,%1,%2,%3}, {%4,%5,%6,%7}, {%8,%9}, {%0,%1,%2,%3};"
        : "+f"(c[0]), "+f"(c[1]), "+f"(c[2]), "+f"(c[3])
        : "r"(a[0]), "r"(a[1]), "r"(a[2]), "r"(a[3]), "r"(b[0]), "r"(b[1]));
}

// =================== tf32 mma.sync GEMM (3-stage cp.async) =================
// EPI: 0 = bias(+add), 1 = bias+gelu, 2 = fused QKV + RoPE
#define AST 36
#define GBUF (128 * AST)

__device__ __forceinline__ void stage_copy(const float* __restrict__ A,
                                           const float* __restrict__ Bt,
                                           int K, int crow, int ccol, int k0,
                                           float* sa, float* sb, int tid)
{
    const int r0 = tid >> 3;
    const int c  = (tid & 7) * 4;
    #pragma unroll
    for (int i = 0; i < 4; i++) {
        const int row = i * 32 + r0;
        cp_async16(smem_u32(sa + row * AST + c), A  + (size_t)(crow + row) * K + k0 + c);
        cp_async16(smem_u32(sb + row * AST + c), Bt + (size_t)(ccol + row) * K + k0 + c);
    }
}

template<int EPI>
__global__ __launch_bounds__(256, 2)
void gemm_mma(const float* __restrict__ A, const float* __restrict__ Bt,
              const float* __restrict__ bias, const float* __restrict__ add,
              float* __restrict__ C, int M, int N, int K,
              float* __restrict__ Ck = nullptr, float* __restrict__ Cv = nullptr)
{
    extern __shared__ float smem[];
    float* As = smem;
    float* Bs = smem + 3 * GBUF;

    const int tid  = threadIdx.x;
    const int wid  = tid >> 5;
    const int lane = tid & 31;
    const int g    = lane >> 2;
    const int t    = lane & 3;

    const int crow = blockIdx.y * 128;
    const int ccol = blockIdx.x * 128;

    const int rb = (wid & 1) * 64;
    const int cb = (wid >> 1) * 32;

    float acc[4][4][4];
    #pragma unroll
    for (int i = 0; i < 4; i++)
        #pragma unroll
        for (int j = 0; j < 4; j++)
            #pragma unroll
            for (int e = 0; e < 4; e++) acc[i][j][e] = 0.f;

    const int niter = K >> 5;

    stage_copy(A, Bt, K, crow, ccol, 0,  As,        Bs,        tid);
    cp_commit();
    stage_copy(A, Bt, K, crow, ccol, 32, As + GBUF, Bs + GBUF, tid);
    cp_commit();

    int buf = 0;
    for (int it = 0; it < niter; ++it) {
        cp_wait<1>();
        __syncthreads();

        const int nbuf = (buf + 2 >= 3) ? buf - 1 : buf + 2;
        if (it + 2 < niter)
            stage_copy(A, Bt, K, crow, ccol, (it + 2) << 5,
                       As + nbuf * GBUF, Bs + nbuf * GBUF, tid);
        cp_commit();

        const float* as = As + buf * GBUF;
        const float* bs = Bs + buf * GBUF;
        #pragma unroll
        for (int kk = 0; kk < 32; kk += 8) {
            uint32_t af[4][4], bf[4][2];
            #pragma unroll
            for (int mt = 0; mt < 4; mt++) {
                const int base = (rb + mt * 16 + g) * AST + kk + t;
                af[mt][0] = __float_as_uint(as[base]);
                af[mt][1] = __float_as_uint(as[base + 8 * AST]);
                af[mt][2] = __float_as_uint(as[base + 4]);
                af[mt][3] = __float_as_uint(as[base + 8 * AST + 4]);
            }
            #pragma unroll
            for (int nt = 0; nt < 4; nt++) {
                const int base = (cb + nt * 8 + g) * AST + kk + t;
                bf[nt][0] = __float_as_uint(bs[base]);
                bf[nt][1] = __float_as_uint(bs[base + 4]);
            }
            #pragma unroll
            for (int mt = 0; mt < 4; mt++)
                #pragma unroll
                for (int nt = 0; nt < 4; nt++)
                    mma_tf32_16x8x8(acc[mt][nt], af[mt], bf[nt]);
        }

        buf = (buf + 1 >= 3) ? 0 : buf + 1;
    }

    // -------- epilogue --------
    float* Cout = C;
    int colmask = ~0;
    bool dorope = false;
    if (EPI == 2) {
        const int sel = ccol >> 10;
        Cout = (sel == 0) ? C : (sel == 1 ? Ck : Cv);
        colmask = 1023;
        dorope = (sel < 2);
    }

    #pragma unroll
    for (int mt = 0; mt < 4; mt++) {
        #pragma unroll
        for (int half = 0; half < 2; half++) {
            const int r = crow + rb + mt * 16 + g + half * 8;
            const int s = r & (SS - 1);
            #pragma unroll
            for (int nt = 0; nt < 4; nt++) {
                const int cg = ccol + cb + nt * 8 + t * 2;
                float v0 = acc[mt][nt][half * 2 + 0] + bias[cg + 0];
                float v1 = acc[mt][nt][half * 2 + 1] + bias[cg + 1];
                if (EPI == 0 || EPI == 1) {
                    if (add) {
                        const float2 a2 = *(const float2*)(add + (size_t)r * N + cg);
                        v0 += a2.x; v1 += a2.y;
                    }
                    if (EPI == 1) {
                        const float t0 = tanh_fast(0.7978845608028654f * (v0 + 0.044715f * v0 * v0 * v0));
                        const float t1 = tanh_fast(0.7978845608028654f * (v1 + 0.044715f * v1 * v1 * v1));
                        v0 = 0.5f * v0 * (1.f + t0);
                        v1 = 0.5f * v1 * (1.f + t1);
                    }
                    *(float2*)(C + (size_t)r * N + cg) = make_float2(v0, v1);
                } else {
                    const int cl = cg & colmask;
                    if (dorope) {
                        const int i = (cl & 63) >> 1;
                        const float2 cs = g_ropetab[s * 32 + i];
                        const float n0 = v0 * cs.x - v1 * cs.y;
                        const float n1 = v1 * cs.x + v0 * cs.y;
                        v0 = n0; v1 = n1;
                    }
                    *(float2*)(Cout + (size_t)r * HD + cl) = make_float2(v0, v1);
                }
            }
        }
    }
}

// ------------- weight transpose + tf32 rounding: in[R,C] -> out[C,R] -------
__global__ __launch_bounds__(256)
void transpose_rna(const float* __restrict__ in, float* __restrict__ out, int R, int C)
{
    __shared__ float t[32][33];
    const int bx = blockIdx.x * 32, by = blockIdx.y * 32;
    const int tx = threadIdx.x, ty = threadIdx.y;
    #pragma unroll
    for (int i = 0; i < 32; i += 8)
        t[ty + i][tx] = in[(size_t)(by + ty + i) * C + bx + tx];
    __syncthreads();
    #pragma unroll
    for (int i = 0; i < 32; i += 8)
        out[(size_t)(bx + ty + i) * R + by + tx] = tf32r(t[tx][ty + i]);
}

// ---------------- rope table + bias pack -----------------------------------
__global__ void rope_tab_kernel() {
    const int s = blockIdx.x;
    const int i = threadIdx.x;
    const float inv = (float)pow(10000.0, -((double)(2 * i)) / 64.0);
    float sn, c;
    sincosf((float)s * inv, &sn, &c);
    g_ropetab[s * 32 + i] = make_float2(c, sn);
}
__global__ void pack_bias_kernel(const float* bq, const float* bk, const float* bv) {
    const int i = blockIdx.x * blockDim.x + threadIdx.x;
    if (i < HD)           g_bqkv[i] = bq[i];
    else if (i < 2 * HD)  g_bqkv[i] = bk[i - HD];
    else if (i < 3 * HD)  g_bqkv[i] = bv[i - 2 * HD];
}

// ============== Flash attention on tensor cores (tf32 mma.sync) ============
// K tiles stride 68 (B-frag bank-bijective via g*4+t), V tiles ROW-major
// stride 72 (B-frag bank-bijective via t*8+g; no transpose, no STS conflicts).
// cp.async double-buffered K/V.
#define ATS 68
#define VST 72
#define KTILE (64 * ATS)
#define VTILE (64 * VST)

__device__ __forceinline__ void attn_copy_kv(const float* __restrict__ kbase,
                                             const float* __restrict__ vbase,
                                             int kt, float* ks, float* vs, int tid)
{
    #pragma unroll
    for (int l = 0; l < 4; l++) {
        const int idx = l * 256 + tid;
        const int r = idx >> 4, c4 = idx & 15;
        cp_async16(smem_u32(ks + r * ATS + c4 * 4), kbase + (size_t)(kt + r) * HD + c4 * 4);
        cp_async16(smem_u32(vs + r * VST + c4 * 4), vbase + (size_t)(kt + r) * HD + c4 * 4);
    }
}

__global__ __launch_bounds__(256, 2)
void attn_mma(const float* __restrict__ Q, const float* __restrict__ Kg,
              const float* __restrict__ Vg, float* __restrict__ O)
{
    extern __shared__ float sm[];
    float* Ks = sm;                         // [2][64*ATS]
    float* Vs = sm + 2 * KTILE;             // [2][64*VST]
    float* Ps = sm + 2 * KTILE + 2 * VTILE; // [128][ATS]

    const int tid  = threadIdx.x;
    const int wid  = tid >> 5;
    const int lane = tid & 31;
    const int g    = lane >> 2;
    const int t    = lane & 3;
    const int rb   = wid * 16;

    const int bh = blockIdx.y;
    const int b  = bh >> 4;
    const int h  = bh & 15;
    const int q0 = blockIdx.x * 128;

    const float qscale = 0.125f * LOG2E;

    const float* kbase = Kg + ((size_t)b * SS) * HD + h * DD;
    const float* vbase = Vg + ((size_t)b * SS) * HD + h * DD;

    // prologue: prefetch tiles 0 and 1
    attn_copy_kv(kbase, vbase, 0,  Ks,         Vs,         tid);
    cp_commit();
    attn_copy_kv(kbase, vbase, 64, Ks + KTILE, Vs + VTILE, tid);
    cp_commit();

    // stage Q tile into Ps (scaled + tf32), pull A fragments
    const float* qbase = Q + ((size_t)(b * SS + q0)) * HD + h * DD;
    #pragma unroll
    for (int l = 0; l < 8; l++) {
        const int idx = l * 256 + tid;
        const int r = idx >> 4, c4 = idx & 15;
        const float4 v4 = *(const float4*)(qbase + (size_t)r * HD + c4 * 4);
        float* d = Ps + r * ATS + c4 * 4;
        d[0] = tf32r(v4.x * qscale); d[1] = tf32r(v4.y * qscale);
        d[2] = tf32r(v4.z * qscale); d[3] = tf32r(v4.w * qscale);
    }
    __syncthreads();

    uint32_t qf[8][4];
    #pragma unroll
    for (int kk = 0; kk < 8; kk++) {
        const int base = (rb + g) * ATS + kk * 8 + t;
        qf[kk][0] = __float_as_uint(Ps[base]);
        qf[kk][1] = __float_as_uint(Ps[base + 8 * ATS]);
        qf[kk][2] = __float_as_uint(Ps[base + 4]);
        qf[kk][3] = __float_as_uint(Ps[base + 8 * ATS + 4]);
    }

    float acc[8][4];
    #pragma unroll
    for (int nt = 0; nt < 8; nt++)
        #pragma unroll
        for (int e = 0; e < 4; e++) acc[nt][e] = 0.f;
    float m0 = -1e30f, m1 = -1e30f, l0 = 0.f, l1 = 0.f;

    for (int it = 0; it < SS / 64; ++it) {
        cp_wait<1>();
        __syncthreads();           // tile it resident; everyone past prior reads
        const float* ks = Ks + (it & 1) * KTILE;
        const float* vs = Vs + (it & 1) * VTILE;

        // ---- S = Q K^T ----
        float s[8][4];
        #pragma unroll
        for (int nt = 0; nt < 8; nt++)
            #pragma unroll
            for (int e = 0; e < 4; e++) s[nt][e] = 0.f;
        #pragma unroll
        for (int kk = 0; kk < 8; kk++) {
            uint32_t bf[8][2];
            #pragma unroll
            for (int nt = 0; nt < 8; nt++) {
                const int base = (nt * 8 + g) * ATS + kk * 8 + t;
                bf[nt][0] = __float_as_uint(ks[base]);
                bf[nt][1] = __float_as_uint(ks[base + 4]);
            }
            #pragma unroll
            for (int nt = 0; nt < 8; nt++)
                mma_tf32_16x8x8(s[nt], qf[kk], bf[nt]);
        }

        // ---- online softmax (base-2) ----
        float rm0 = s[0][0], rm1 = s[0][2];
        #pragma unroll
        for (int nt = 0; nt < 8; nt++) {
            rm0 = fmaxf(rm0, fmaxf(s[nt][0], s[nt][1]));
            rm1 = fmaxf(rm1, fmaxf(s[nt][2], s[nt][3]));
        }
        rm0 = fmaxf(rm0, __shfl_xor_sync(0xffffffffu, rm0, 1));
        rm0 = fmaxf(rm0, __shfl_xor_sync(0xffffffffu, rm0, 2));
        rm1 = fmaxf(rm1, __shfl_xor_sync(0xffffffffu, rm1, 1));
        rm1 = fmaxf(rm1, __shfl_xor_sync(0xffffffffu, rm1, 2));
        const float mt0 = fmaxf(m0, rm0);
        const float mt1 = fmaxf(m1, rm1);
        if (mt0 > m0) {
            const float c0 = fexp2(m0 - mt0);
            l0 *= c0;
            #pragma unroll
            for (int nt = 0; nt < 8; nt++) { acc[nt][0] *= c0; acc[nt][1] *= c0; }
            m0 = mt0;
        }
        if (mt1 > m1) {
            const float c1 = fexp2(m1 - mt1);
            l1 *= c1;
            #pragma unroll
            for (int nt = 0; nt < 8; nt++) { acc[nt][2] *= c1; acc[nt][3] *= c1; }
            m1 = mt1;
        }

        float ps0 = 0.f, ps1 = 0.f;
        #pragma unroll
        for (int nt = 0; nt < 8; nt++) {
            const float p00 = tf32r(fexp2(s[nt][0] - m0));
            const float p01 = tf32r(fexp2(s[nt][1] - m0));
            const float p10 = tf32r(fexp2(s[nt][2] - m1));
            const float p11 = tf32r(fexp2(s[nt][3] - m1));
            ps0 += p00 + p01;
            ps1 += p10 + p11;
            *(float2*)&Ps[(rb + g) * ATS + nt * 8 + 2 * t]     = make_float2(p00, p01);
            *(float2*)&Ps[(rb + g + 8) * ATS + nt * 8 + 2 * t] = make_float2(p10, p11);
        }
        ps0 += __shfl_xor_sync(0xffffffffu, ps0, 1);
        ps0 += __shfl_xor_sync(0xffffffffu, ps0, 2);
        ps1 += __shfl_xor_sync(0xffffffffu, ps1, 1);
        ps1 += __shfl_xor_sync(0xffffffffu, ps1, 2);
        l0 += ps0;
        l1 += ps1;
        __syncwarp();   // Ps region is per-warp

        // ---- acc += P V  (B-frag from row-major Vs, stride 72) ----
        #pragma unroll
        for (int kk = 0; kk < 8; kk++) {
            uint32_t af[4];
            const int base = (rb + g) * ATS + kk * 8 + t;
            af[0] = __float_as_uint(Ps[base]);
            af[1] = __float_as_uint(Ps[base + 8 * ATS]);
            af[2] = __float_as_uint(Ps[base + 4]);
            af[3] = __float_as_uint(Ps[base + 8 * ATS + 4]);
            const int vrow0 = (kk * 8 + t) * VST;
            const int vrow1 = (kk * 8 + t + 4) * VST;
            #pragma unroll
            for (int nt = 0; nt < 8; nt++) {
                uint32_t bf[2];
                bf[0] = __float_as_uint(vs[vrow0 + nt * 8 + g]);
                bf[1] = __float_as_uint(vs[vrow1 + nt * 8 + g]);
                mma_tf32_16x8x8(acc[nt], af, bf);
            }
        }

        __syncthreads();           // all warps done with buffer (it&1)
        if (it + 2 < SS / 64)
            attn_copy_kv(kbase, vbase, (it + 2) * 64,
                         Ks + (it & 1) * KTILE, Vs + (it & 1) * VTILE, tid);
        cp_commit();
    }

    const float i0 = 1.f / l0;
    const float i1 = 1.f / l1;
    const int r0 = q0 + rb + g;
    const int r1 = r0 + 8;
    float* o0 = O + ((size_t)(b * SS + r0)) * HD + h * DD;
    float* o1 = O + ((size_t)(b * SS + r1)) * HD + h * DD;
    #pragma unroll
    for (int nt = 0; nt < 8; nt++) {
        *(float2*)(o0 + nt * 8 + 2 * t) = make_float2(acc[nt][0] * i0, acc[nt][1] * i0);
        *(float2*)(o1 + nt * 8 + 2 * t) = make_float2(acc[nt][2] * i1, acc[nt][3] * i1);
    }
}

// -------- LayerNorm over last dim (1024), eps=1e-12, single-pass -----------
__global__ __launch_bounds__(256)
void ln_kernel(const float* __restrict__ in, const float* __restrict__ gamma,
               const float* __restrict__ beta, float* __restrict__ out)
{
    const int row = blockIdx.x;
    const int tid = threadIdx.x;
    const float4 xv = ((const float4*)(in + (size_t)row * HD))[tid];

    __shared__ float2 red[8];
    float s  = xv.x + xv.y + xv.z + xv.w;
    float sq = xv.x*xv.x + xv.y*xv.y + xv.z*xv.z + xv.w*xv.w;
    #pragma unroll
    for (int o = 16; o > 0; o >>= 1) {
        s  += __shfl_xor_sync(0xffffffffu, s,  o);
        sq += __shfl_xor_sync(0xffffffffu, sq, o);
    }
    if ((tid & 31) == 0) red[tid >> 5] = make_float2(s, sq);
    __syncthreads();
    if (tid < 32) {
        float2 v = (tid < 8) ? red[tid] : make_float2(0.f, 0.f);
        float a = v.x, b2 = v.y;
        #pragma unroll
        for (int o = 4; o > 0; o >>= 1) {
            a  += __shfl_xor_sync(0xffffffffu, a,  o);
            b2 += __shfl_xor_sync(0xffffffffu, b2, o);
        }
        if (tid == 0) red[0] = make_float2(a, b2);
    }
    __syncthreads();
    const float mu   = red[0].x * (1.f / 1024.f);
    const float var  = red[0].y * (1.f / 1024.f) - mu * mu;
    const float rstd = rsqrtf(var + 1e-12f);

    const float4 gv = ((const float4*)gamma)[tid];
    const float4 bv = ((const float4*)beta )[tid];
    float4 ov;
    ov.x = (xv.x - mu) * rstd * gv.x + bv.x;
    ov.y = (xv.y - mu) * rstd * gv.y + bv.y;
    ov.z = (xv.z - mu) * rstd * gv.z + bv.z;
    ov.w = (xv.w - mu) * rstd * gv.w + bv.w;
    ((float4*)(out + (size_t)row * HD))[tid] = ov;
}

// ---------------- launch ----------------------------------------------------
extern "C" void kernel_launch(void* const* d_in, const int* in_sizes, int n_in,
                              void* d_out, int out_size)
{
    const float* x     = (const float*)d_in[0];
    const float* Wq    = (const float*)d_in[1];
    const float* bq    = (const float*)d_in[2];
    const float* Wk    = (const float*)d_in[3];
    const float* bk    = (const float*)d_in[4];
    const float* Wv    = (const float*)d_in[5];
    const float* bv    = (const float*)d_in[6];
    const float* Wo    = (const float*)d_in[7];
    const float* bo    = (const float*)d_in[8];
    const float* g1    = (const float*)d_in[9];
    const float* beta1 = (const float*)d_in[10];
    const float* W1    = (const float*)d_in[11];
    const float* b1    = (const float*)d_in[12];
    const float* W2    = (const float*)d_in[13];
    const float* b2    = (const float*)d_in[14];
    const float* g2    = (const float*)d_in[15];
    const float* beta2 = (const float*)d_in[16];
    float* out = (float*)d_out;

    float *q, *k, *v, *ctx, *r1, *h, *ff, *r2;
    float *wqkvt, *bqkv, *wot, *w1t, *w2t;
    cudaGetSymbolAddress((void**)&q,     g_q);
    cudaGetSymbolAddress((void**)&k,     g_k);
    cudaGetSymbolAddress((void**)&v,     g_v);
    cudaGetSymbolAddress((void**)&ctx,   g_ctx);
    cudaGetSymbolAddress((void**)&r1,    g_r1);
    cudaGetSymbolAddress((void**)&h,     g_h);
    cudaGetSymbolAddress((void**)&ff,    g_ff);
    cudaGetSymbolAddress((void**)&r2,    g_r2);
    cudaGetSymbolAddress((void**)&wqkvt, g_wqkvt);
    cudaGetSymbolAddress((void**)&bqkv,  g_bqkv);
    cudaGetSymbolAddress((void**)&wot,   g_wot);
    cudaGetSymbolAddress((void**)&w1t,   g_w1t);
    cudaGetSymbolAddress((void**)&w2t,   g_w2t);

    const int GEMM_SMEM = 6 * GBUF * 4;                         // 110592 B
    const int ATT_SMEM  = (2 * KTILE + 2 * VTILE + 128 * ATS) * 4;  // 106496 B
    cudaFuncSetAttribute(gemm_mma<0>, cudaFuncAttributeMaxDynamicSharedMemorySize, GEMM_SMEM);
    cudaFuncSetAttribute(gemm_mma<1>, cudaFuncAttributeMaxDynamicSharedMemorySize, GEMM_SMEM);
    cudaFuncSetAttribute(gemm_mma<2>, cudaFuncAttributeMaxDynamicSharedMemorySize, GEMM_SMEM);
    cudaFuncSetAttribute(attn_mma, cudaFuncAttributeMaxDynamicSharedMemorySize, ATT_SMEM);

    // tables + packed transposed weights
    rope_tab_kernel<<<SS, 32>>>();
    pack_bias_kernel<<<(3 * HD + 255) / 256, 256>>>(bq, bk, bv);
    const dim3 tb(32, 8);
    transpose_rna<<<dim3(HD / 32,  HD / 32),  tb>>>(Wq, wqkvt,               HD,  HD);
    transpose_rna<<<dim3(HD / 32,  HD / 32),  tb>>>(Wk, wqkvt + HD * HD,     HD,  HD);
    transpose_rna<<<dim3(HD / 32,  HD / 32),  tb>>>(Wv, wqkvt + 2 * HD * HD, HD,  HD);
    transpose_rna<<<dim3(HD / 32,  HD / 32),  tb>>>(Wo, wot, HD,  HD);
    transpose_rna<<<dim3(FFD / 32, HD / 32),  tb>>>(W1, w1t, HD,  FFD);
    transpose_rna<<<dim3(HD / 32,  FFD / 32), tb>>>(W2, w2t, FFD, HD);

    const dim3 gQKV(3 * HD / 128, BSR / 128);  // (24, 64)
    const dim3 gHd (HD  / 128,    BSR / 128);  // (8, 64)
    const dim3 gFf (FFD / 128,    BSR / 128);  // (32, 64)

    // fused QKV projection + bias + RoPE
    gemm_mma<2><<<gQKV, 256, GEMM_SMEM>>>(x, wqkvt, bqkv, nullptr, q, BSR, HD, HD, k, v);

    // Flash attention on tensor cores -> ctx
    attn_mma<<<dim3(SS / 128, BB * NHH), 256, ATT_SMEM>>>(q, k, v, ctx);

    // O projection + residual(x) -> r1 ; LN -> h
    gemm_mma<0><<<gHd, 256, GEMM_SMEM>>>(ctx, wot, bo, x, r1, BSR, HD, HD);
    ln_kernel<<<BSR, 256>>>(r1, g1, beta1, h);

    // FFN
    gemm_mma<1><<<gFf, 256, GEMM_SMEM>>>(h,  w1t, b1, nullptr, ff, BSR, FFD, HD);
    gemm_mma<0><<<gHd, 256, GEMM_SMEM>>>(ff, w2t, b2, h,       r2, BSR, HD, FFD);

    // final LN -> out
    ln_kernel<<<BSR, 256>>>(r2, g2, beta2, out);
}

// round 13
// speedup vs baseline: 4.2876x; 1.0051x over previous
#include <cuda_runtime.h>
#include <cuda_bf16.h>
#include <math.h>
#include <stdint.h>

// Problem constants
#define BB   4
#define SS   2048
#define HD   1024
#define NHH  16
#define DD   64
#define FFD  4096
#define BSR  (BB*SS)          // 8192 rows
#define LOG2E 1.4426950408889634f

// ---------------- scratch (device globals: no allocation allowed) ----------
__device__ float g_q  [BSR * HD];
__device__ float g_k  [BSR * HD];
__device__ float g_v  [BSR * HD];
__device__ float g_ctx[BSR * HD];
__device__ float g_r1 [BSR * HD];
__device__ float g_h  [BSR * HD];
__device__ float g_ff [BSR * FFD];
__device__ float g_r2 [BSR * HD];
// packed transposed (N,K) tf32-rounded weights
__device__ float g_wqkvt[3 * HD * HD];
__device__ float g_bqkv [3 * HD];
__device__ float g_wot[HD * HD];
__device__ float g_w1t[FFD * HD];
__device__ float g_w2t[HD * FFD];
// rope cos/sin table [S][32]
__device__ float2 g_ropetab[SS * 32];

__device__ __forceinline__ float tf32r(float x) {
    float r;
    asm("cvt.rna.tf32.f32 %0, %1;" : "=f"(r) : "f"(x));
    return r;
}
__device__ __forceinline__ float tanh_fast(float x) {
    float y;
    asm("tanh.approx.f32 %0, %1;" : "=f"(y) : "f"(x));
    return y;
}
__device__ __forceinline__ uint32_t smem_u32(const void* p) {
    uint32_t a;
    asm("{ .reg .u64 t; cvta.to.shared.u64 t, %1; cvt.u32.u64 %0, t; }" : "=r"(a) : "l"(p));
    return a;
}
__device__ __forceinline__ void cp_async16(uint32_t saddr, const void* g) {
    asm volatile("cp.async.cg.shared.global [%0], [%1], 16;" :: "r"(saddr), "l"(g));
}
__device__ __forceinline__ void cp_commit() {
    asm volatile("cp.async.commit_group;" ::: "memory");
}
template<int N> __device__ __forceinline__ void cp_wait() {
    asm volatile("cp.async.wait_group %0;" :: "n"(N) : "memory");
}

// fast exp2 on the fma/alu pipes (valid for x <= ~0; clamps at -126)
__device__ __forceinline__ float fexp2(float x) {
    x = fmaxf(x, -126.f);
    const float k = x + 12582912.f;
    const int   ik = __float_as_int(k) - 0x4B400000;
    const float f = x - (k - 12582912.f);
    float p = 9.6181291e-3f;
    p = fmaf(p, f, 5.5504109e-2f);
    p = fmaf(p, f, 2.4022651e-1f);
    p = fmaf(p, f, 6.9314718e-1f);
    p = fmaf(p, f, 1.0f);
    return __int_as_float(__float_as_int(p) + (ik << 23));
}

__device__ __forceinline__ void mma_tf32_16x8x8(float* c, const uint32_t* a, const uint32_t* b) {
    asm volatile(
        "mma.sync.aligned.m16n8k8.row.col.f32.tf32.tf32.f32 "
        "{%0,%1,%2,%3}, {%4,%5,%6,%7}, {%8,%9}, {%0,%1,%2,%3};"
        : "+f"(c[0]), "+f"(c[1]), "+f"(c[2]), "+f"(c[3])
        : "r"(a[0]), "r"(a[1]), "r"(a[2]), "r"(a[3]), "r"(b[0]), "r"(b[1]));
}

// =================== tf32 mma.sync GEMM (3-stage cp.async) =================
// EPI: 0 = bias(+add), 1 = bias+gelu, 2 = fused QKV + RoPE
// BM=BN=128, BK=32, **128 threads (4 warps), warp tile 64x64** for 2x
// register-level reuse: 32 LDS words per 64K FLOP per k-step (16 FLOP/B).
#define AST 36
#define GBUF (128 * AST)

__device__ __forceinline__ void stage_copy(const float* __restrict__ A,
                                           const float* __restrict__ Bt,
                                           int K, int crow, int ccol, int k0,
                                           float* sa, float* sb, int tid)
{
    const int r0 = tid >> 3;          // 0..15
    const int c  = (tid & 7) * 4;     // 0..28
    #pragma unroll
    for (int i = 0; i < 8; i++) {
        const int row = i * 16 + r0;
        cp_async16(smem_u32(sa + row * AST + c), A  + (size_t)(crow + row) * K + k0 + c);
        cp_async16(smem_u32(sb + row * AST + c), Bt + (size_t)(ccol + row) * K + k0 + c);
    }
}

template<int EPI>
__global__ __launch_bounds__(128, 2)
void gemm_mma(const float* __restrict__ A, const float* __restrict__ Bt,
              const float* __restrict__ bias, const float* __restrict__ add,
              float* __restrict__ C, int M, int N, int K,
              float* __restrict__ Ck = nullptr, float* __restrict__ Cv = nullptr)
{
    extern __shared__ float smem[];
    float* As = smem;
    float* Bs = smem + 3 * GBUF;

    const int tid  = threadIdx.x;
    const int wid  = tid >> 5;        // 0..3
    const int lane = tid & 31;
    const int g    = lane >> 2;
    const int t    = lane & 3;

    const int crow = blockIdx.y * 128;
    const int ccol = blockIdx.x * 128;

    const int rb = (wid & 1) * 64;    // 2x2 warp grid, 64x64 tiles
    const int cb = (wid >> 1) * 64;

    float acc[4][8][4];
    #pragma unroll
    for (int i = 0; i < 4; i++)
        #pragma unroll
        for (int j = 0; j < 8; j++)
            #pragma unroll
            for (int e = 0; e < 4; e++) acc[i][j][e] = 0.f;

    const int niter = K >> 5;

    stage_copy(A, Bt, K, crow, ccol, 0,  As,        Bs,        tid);
    cp_commit();
    stage_copy(A, Bt, K, crow, ccol, 32, As + GBUF, Bs + GBUF, tid);
    cp_commit();

    int buf = 0;
    for (int it = 0; it < niter; ++it) {
        cp_wait<1>();
        __syncthreads();

        const int nbuf = (buf + 2 >= 3) ? buf - 1 : buf + 2;
        if (it + 2 < niter)
            stage_copy(A, Bt, K, crow, ccol, (it + 2) << 5,
                       As + nbuf * GBUF, Bs + nbuf * GBUF, tid);
        cp_commit();

        const float* as = As + buf * GBUF;
        const float* bs = Bs + buf * GBUF;
        #pragma unroll
        for (int kk = 0; kk < 32; kk += 8) {
            uint32_t af[4][4], bf[8][2];
            #pragma unroll
            for (int mt = 0; mt < 4; mt++) {
                const int base = (rb + mt * 16 + g) * AST + kk + t;
                af[mt][0] = __float_as_uint(as[base]);
                af[mt][1] = __float_as_uint(as[base + 8 * AST]);
                af[mt][2] = __float_as_uint(as[base + 4]);
                af[mt][3] = __float_as_uint(as[base + 8 * AST + 4]);
            }
            #pragma unroll
            for (int nt = 0; nt < 8; nt++) {
                const int base = (cb + nt * 8 + g) * AST + kk + t;
                bf[nt][0] = __float_as_uint(bs[base]);
                bf[nt][1] = __float_as_uint(bs[base + 4]);
            }
            #pragma unroll
            for (int mt = 0; mt < 4; mt++)
                #pragma unroll
                for (int nt = 0; nt < 8; nt++)
                    mma_tf32_16x8x8(acc[mt][nt], af[mt], bf[nt]);
        }

        buf = (buf + 1 >= 3) ? 0 : buf + 1;
    }

    // -------- epilogue --------
    float* Cout = C;
    int colmask = ~0;
    bool dorope = false;
    if (EPI == 2) {
        const int sel = ccol >> 10;
        Cout = (sel == 0) ? C : (sel == 1 ? Ck : Cv);
        colmask = 1023;
        dorope = (sel < 2);
    }

    #pragma unroll
    for (int mt = 0; mt < 4; mt++) {
        #pragma unroll
        for (int half = 0; half < 2; half++) {
            const int r = crow + rb + mt * 16 + g + half * 8;
            const int s = r & (SS - 1);
            #pragma unroll
            for (int nt = 0; nt < 8; nt++) {
                const int cg = ccol + cb + nt * 8 + t * 2;
                float v0 = acc[mt][nt][half * 2 + 0] + bias[cg + 0];
                float v1 = acc[mt][nt][half * 2 + 1] + bias[cg + 1];
                if (EPI == 0 || EPI == 1) {
                    if (add) {
                        const float2 a2 = *(const float2*)(add + (size_t)r * N + cg);
                        v0 += a2.x; v1 += a2.y;
                    }
                    if (EPI == 1) {
                        const float t0 = tanh_fast(0.7978845608028654f * (v0 + 0.044715f * v0 * v0 * v0));
                        const float t1 = tanh_fast(0.7978845608028654f * (v1 + 0.044715f * v1 * v1 * v1));
                        v0 = 0.5f * v0 * (1.f + t0);
                        v1 = 0.5f * v1 * (1.f + t1);
                    }
                    *(float2*)(C + (size_t)r * N + cg) = make_float2(v0, v1);
                } else {
                    const int cl = cg & colmask;
                    if (dorope) {
                        const int i = (cl & 63) >> 1;
                        const float2 cs = g_ropetab[s * 32 + i];
                        const float n0 = v0 * cs.x - v1 * cs.y;
                        const float n1 = v1 * cs.x + v0 * cs.y;
                        v0 = n0; v1 = n1;
                    }
                    *(float2*)(Cout + (size_t)r * HD + cl) = make_float2(v0, v1);
                }
            }
        }
    }
}

// ------------- weight transpose + tf32 rounding: in[R,C] -> out[C,R] -------
__global__ __launch_bounds__(256)
void transpose_rna(const float* __restrict__ in, float* __restrict__ out, int R, int C)
{
    __shared__ float t[32][33];
    const int bx = blockIdx.x * 32, by = blockIdx.y * 32;
    const int tx = threadIdx.x, ty = threadIdx.y;
    #pragma unroll
    for (int i = 0; i < 32; i += 8)
        t[ty + i][tx] = in[(size_t)(by + ty + i) * C + bx + tx];
    __syncthreads();
    #pragma unroll
    for (int i = 0; i < 32; i += 8)
        out[(size_t)(bx + ty + i) * R + by + tx] = tf32r(t[tx][ty + i]);
}

// ---------------- rope table + bias pack -----------------------------------
__global__ void rope_tab_kernel() {
    const int s = blockIdx.x;
    const int i = threadIdx.x;
    const float inv = (float)pow(10000.0, -((double)(2 * i)) / 64.0);
    float sn, c;
    sincosf((float)s * inv, &sn, &c);
    g_ropetab[s * 32 + i] = make_float2(c, sn);
}
__global__ void pack_bias_kernel(const float* bq, const float* bk, const float* bv) {
    const int i = blockIdx.x * blockDim.x + threadIdx.x;
    if (i < HD)           g_bqkv[i] = bq[i];
    else if (i < 2 * HD)  g_bqkv[i] = bk[i - HD];
    else if (i < 3 * HD)  g_bqkv[i] = bv[i - 2 * HD];
}

// ============== Flash attention on tensor cores (tf32 mma.sync) ============
#define ATS 68
#define VST 72
#define KTILE (64 * ATS)
#define VTILE (64 * VST)

__device__ __forceinline__ void attn_copy_kv(const float* __restrict__ kbase,
                                             const float* __restrict__ vbase,
                                             int kt, float* ks, float* vs, int tid)
{
    #pragma unroll
    for (int l = 0; l < 4; l++) {
        const int idx = l * 256 + tid;
        const int r = idx >> 4, c4 = idx & 15;
        cp_async16(smem_u32(ks + r * ATS + c4 * 4), kbase + (size_t)(kt + r) * HD + c4 * 4);
        cp_async16(smem_u32(vs + r * VST + c4 * 4), vbase + (size_t)(kt + r) * HD + c4 * 4);
    }
}

__global__ __launch_bounds__(256, 2)
void attn_mma(const float* __restrict__ Q, const float* __restrict__ Kg,
              const float* __restrict__ Vg, float* __restrict__ O)
{
    extern __shared__ float sm[];
    float* Ks = sm;
    float* Vs = sm + 2 * KTILE;
    float* Ps = sm + 2 * KTILE + 2 * VTILE;

    const int tid  = threadIdx.x;
    const int wid  = tid >> 5;
    const int lane = tid & 31;
    const int g    = lane >> 2;
    const int t    = lane & 3;
    const int rb   = wid * 16;

    const int bh = blockIdx.y;
    const int b  = bh >> 4;
    const int h  = bh & 15;
    const int q0 = blockIdx.x * 128;

    const float qscale = 0.125f * LOG2E;

    const float* kbase = Kg + ((size_t)b * SS) * HD + h * DD;
    const float* vbase = Vg + ((size_t)b * SS) * HD + h * DD;

    attn_copy_kv(kbase, vbase, 0,  Ks,         Vs,         tid);
    cp_commit();
    attn_copy_kv(kbase, vbase, 64, Ks + KTILE, Vs + VTILE, tid);
    cp_commit();

    const float* qbase = Q + ((size_t)(b * SS + q0)) * HD + h * DD;
    #pragma unroll
    for (int l = 0; l < 8; l++) {
        const int idx = l * 256 + tid;
        const int r = idx >> 4, c4 = idx & 15;
        const float4 v4 = *(const float4*)(qbase + (size_t)r * HD + c4 * 4);
        float* d = Ps + r * ATS + c4 * 4;
        d[0] = tf32r(v4.x * qscale); d[1] = tf32r(v4.y * qscale);
        d[2] = tf32r(v4.z * qscale); d[3] = tf32r(v4.w * qscale);
    }
    __syncthreads();

    uint32_t qf[8][4];
    #pragma unroll
    for (int kk = 0; kk < 8; kk++) {
        const int base = (rb + g) * ATS + kk * 8 + t;
        qf[kk][0] = __float_as_uint(Ps[base]);
        qf[kk][1] = __float_as_uint(Ps[base + 8 * ATS]);
        qf[kk][2] = __float_as_uint(Ps[base + 4]);
        qf[kk][3] = __float_as_uint(Ps[base + 8 * ATS + 4]);
    }

    float acc[8][4];
    #pragma unroll
    for (int nt = 0; nt < 8; nt++)
        #pragma unroll
        for (int e = 0; e < 4; e++) acc[nt][e] = 0.f;
    float m0 = -1e30f, m1 = -1e30f, l0 = 0.f, l1 = 0.f;

    for (int it = 0; it < SS / 64; ++it) {
        cp_wait<1>();
        __syncthreads();
        const float* ks = Ks + (it & 1) * KTILE;
        const float* vs = Vs + (it & 1) * VTILE;

        float s[8][4];
        #pragma unroll
        for (int nt = 0; nt < 8; nt++)
            #pragma unroll
            for (int e = 0; e < 4; e++) s[nt][e] = 0.f;
        #pragma unroll
        for (int kk = 0; kk < 8; kk++) {
            uint32_t bf[8][2];
            #pragma unroll
            for (int nt = 0; nt < 8; nt++) {
                const int base = (nt * 8 + g) * ATS + kk * 8 + t;
                bf[nt][0] = __float_as_uint(ks[base]);
                bf[nt][1] = __float_as_uint(ks[base + 4]);
            }
            #pragma unroll
            for (int nt = 0; nt < 8; nt++)
                mma_tf32_16x8x8(s[nt], qf[kk], bf[nt]);
        }

        float rm0 = s[0][0], rm1 = s[0][2];
        #pragma unroll
        for (int nt = 0; nt < 8; nt++) {
            rm0 = fmaxf(rm0, fmaxf(s[nt][0], s[nt][1]));
            rm1 = fmaxf(rm1, fmaxf(s[nt][2], s[nt][3]));
        }
        rm0 = fmaxf(rm0, __shfl_xor_sync(0xffffffffu, rm0, 1));
        rm0 = fmaxf(rm0, __shfl_xor_sync(0xffffffffu, rm0, 2));
        rm1 = fmaxf(rm1, __shfl_xor_sync(0xffffffffu, rm1, 1));
        rm1 = fmaxf(rm1, __shfl_xor_sync(0xffffffffu, rm1, 2));
        const float mt0 = fmaxf(m0, rm0);
        const float mt1 = fmaxf(m1, rm1);
        if (mt0 > m0) {
            const float c0 = fexp2(m0 - mt0);
            l0 *= c0;
            #pragma unroll
            for (int nt = 0; nt < 8; nt++) { acc[nt][0] *= c0; acc[nt][1] *= c0; }
            m0 = mt0;
        }
        if (mt1 > m1) {
            const float c1 = fexp2(m1 - mt1);
            l1 *= c1;
            #pragma unroll
            for (int nt = 0; nt < 8; nt++) { acc[nt][2] *= c1; acc[nt][3] *= c1; }
            m1 = mt1;
        }

        float ps0 = 0.f, ps1 = 0.f;
        #pragma unroll
        for (int nt = 0; nt < 8; nt++) {
            const float p00 = tf32r(fexp2(s[nt][0] - m0));
            const float p01 = tf32r(fexp2(s[nt][1] - m0));
            const float p10 = tf32r(fexp2(s[nt][2] - m1));
            const float p11 = tf32r(fexp2(s[nt][3] - m1));
            ps0 += p00 + p01;
            ps1 += p10 + p11;
            *(float2*)&Ps[(rb + g) * ATS + nt * 8 + 2 * t]     = make_float2(p00, p01);
            *(float2*)&Ps[(rb + g + 8) * ATS + nt * 8 + 2 * t] = make_float2(p10, p11);
        }
        ps0 += __shfl_xor_sync(0xffffffffu, ps0, 1);
        ps0 += __shfl_xor_sync(0xffffffffu, ps0, 2);
        ps1 += __shfl_xor_sync(0xffffffffu, ps1, 1);
        ps1 += __shfl_xor_sync(0xffffffffu, ps1, 2);
        l0 += ps0;
        l1 += ps1;
        __syncwarp();

        #pragma unroll
        for (int kk = 0; kk < 8; kk++) {
            uint32_t af[4];
            const int base = (rb + g) * ATS + kk * 8 + t;
            af[0] = __float_as_uint(Ps[base]);
            af[1] = __float_as_uint(Ps[base + 8 * ATS]);
            af[2] = __float_as_uint(Ps[base + 4]);
            af[3] = __float_as_uint(Ps[base + 8 * ATS + 4]);
            const int vrow0 = (kk * 8 + t) * VST;
            const int vrow1 = (kk * 8 + t + 4) * VST;
            #pragma unroll
            for (int nt = 0; nt < 8; nt++) {
                uint32_t bf[2];
                bf[0] = __float_as_uint(vs[vrow0 + nt * 8 + g]);
                bf[1] = __float_as_uint(vs[vrow1 + nt * 8 + g]);
                mma_tf32_16x8x8(acc[nt], af, bf);
            }
        }

        __syncthreads();
        if (it + 2 < SS / 64)
            attn_copy_kv(kbase, vbase, (it + 2) * 64,
                         Ks + (it & 1) * KTILE, Vs + (it & 1) * VTILE, tid);
        cp_commit();
    }

    const float i0 = 1.f / l0;
    const float i1 = 1.f / l1;
    const int r0 = q0 + rb + g;
    const int r1 = r0 + 8;
    float* o0 = O + ((size_t)(b * SS + r0)) * HD + h * DD;
    float* o1 = O + ((size_t)(b * SS + r1)) * HD + h * DD;
    #pragma unroll
    for (int nt = 0; nt < 8; nt++) {
        *(float2*)(o0 + nt * 8 + 2 * t) = make_float2(acc[nt][0] * i0, acc[nt][1] * i0);
        *(float2*)(o1 + nt * 8 + 2 * t) = make_float2(acc[nt][2] * i1, acc[nt][3] * i1);
    }
}

// -------- LayerNorm over last dim (1024), eps=1e-12, single-pass -----------
__global__ __launch_bounds__(256)
void ln_kernel(const float* __restrict__ in, const float* __restrict__ gamma,
               const float* __restrict__ beta, float* __restrict__ out)
{
    const int row = blockIdx.x;
    const int tid = threadIdx.x;
    const float4 xv = ((const float4*)(in + (size_t)row * HD))[tid];

    __shared__ float2 red[8];
    float s  = xv.x + xv.y + xv.z + xv.w;
    float sq = xv.x*xv.x + xv.y*xv.y + xv.z*xv.z + xv.w*xv.w;
    #pragma unroll
    for (int o = 16; o > 0; o >>= 1) {
        s  += __shfl_xor_sync(0xffffffffu, s,  o);
        sq += __shfl_xor_sync(0xffffffffu, sq, o);
    }
    if ((tid & 31) == 0) red[tid >> 5] = make_float2(s, sq);
    __syncthreads();
    if (tid < 32) {
        float2 v = (tid < 8) ? red[tid] : make_float2(0.f, 0.f);
        float a = v.x, b2 = v.y;
        #pragma unroll
        for (int o = 4; o > 0; o >>= 1) {
            a  += __shfl_xor_sync(0xffffffffu, a,  o);
            b2 += __shfl_xor_sync(0xffffffffu, b2, o);
        }
        if (tid == 0) red[0] = make_float2(a, b2);
    }
    __syncthreads();
    const float mu   = red[0].x * (1.f / 1024.f);
    const float var  = red[0].y * (1.f / 1024.f) - mu * mu;
    const float rstd = rsqrtf(var + 1e-12f);

    const float4 gv = ((const float4*)gamma)[tid];
    const float4 bv = ((const float4*)beta )[tid];
    float4 ov;
    ov.x = (xv.x - mu) * rstd * gv.x + bv.x;
    ov.y = (xv.y - mu) * rstd * gv.y + bv.y;
    ov.z = (xv.z - mu) * rstd * gv.z + bv.z;
    ov.w = (xv.w - mu) * rstd * gv.w + bv.w;
    ((float4*)(out + (size_t)row * HD))[tid] = ov;
}

// ---------------- launch ----------------------------------------------------
extern "C" void kernel_launch(void* const* d_in, const int* in_sizes, int n_in,
                              void* d_out, int out_size)
{
    const float* x     = (const float*)d_in[0];
    const float* Wq    = (const float*)d_in[1];
    const float* bq    = (const float*)d_in[2];
    const float* Wk    = (const float*)d_in[3];
    const float* bk    = (const float*)d_in[4];
    const float* Wv    = (const float*)d_in[5];
    const float* bv    = (const float*)d_in[6];
    const float* Wo    = (const float*)d_in[7];
    const float* bo    = (const float*)d_in[8];
    const float* g1    = (const float*)d_in[9];
    const float* beta1 = (const float*)d_in[10];
    const float* W1    = (const float*)d_in[11];
    const float* b1    = (const float*)d_in[12];
    const float* W2    = (const float*)d_in[13];
    const float* b2    = (const float*)d_in[14];
    const float* g2    = (const float*)d_in[15];
    const float* beta2 = (const float*)d_in[16];
    float* out = (float*)d_out;

    float *q, *k, *v, *ctx, *r1, *h, *ff, *r2;
    float *wqkvt, *bqkv, *wot, *w1t, *w2t;
    cudaGetSymbolAddress((void**)&q,     g_q);
    cudaGetSymbolAddress((void**)&k,     g_k);
    cudaGetSymbolAddress((void**)&v,     g_v);
    cudaGetSymbolAddress((void**)&ctx,   g_ctx);
    cudaGetSymbolAddress((void**)&r1,    g_r1);
    cudaGetSymbolAddress((void**)&h,     g_h);
    cudaGetSymbolAddress((void**)&ff,    g_ff);
    cudaGetSymbolAddress((void**)&r2,    g_r2);
    cudaGetSymbolAddress((void**)&wqkvt, g_wqkvt);
    cudaGetSymbolAddress((void**)&bqkv,  g_bqkv);
    cudaGetSymbolAddress((void**)&wot,   g_wot);
    cudaGetSymbolAddress((void**)&w1t,   g_w1t);
    cudaGetSymbolAddress((void**)&w2t,   g_w2t);

    const int GEMM_SMEM = 6 * GBUF * 4;                             // 110592 B
    const int ATT_SMEM  = (2 * KTILE + 2 * VTILE + 128 * ATS) * 4;  // 106496 B
    cudaFuncSetAttribute(gemm_mma<0>, cudaFuncAttributeMaxDynamicSharedMemorySize, GEMM_SMEM);
    cudaFuncSetAttribute(gemm_mma<1>, cudaFuncAttributeMaxDynamicSharedMemorySize, GEMM_SMEM);
    cudaFuncSetAttribute(gemm_mma<2>, cudaFuncAttributeMaxDynamicSharedMemorySize, GEMM_SMEM);
    cudaFuncSetAttribute(attn_mma, cudaFuncAttributeMaxDynamicSharedMemorySize, ATT_SMEM);

    // tables + packed transposed weights
    rope_tab_kernel<<<SS, 32>>>();
    pack_bias_kernel<<<(3 * HD + 255) / 256, 256>>>(bq, bk, bv);
    const dim3 tb(32, 8);
    transpose_rna<<<dim3(HD / 32,  HD / 32),  tb>>>(Wq, wqkvt,               HD,  HD);
    transpose_rna<<<dim3(HD / 32,  HD / 32),  tb>>>(Wk, wqkvt + HD * HD,     HD,  HD);
    transpose_rna<<<dim3(HD / 32,  HD / 32),  tb>>>(Wv, wqkvt + 2 * HD * HD, HD,  HD);
    transpose_rna<<<dim3(HD / 32,  HD / 32),  tb>>>(Wo, wot, HD,  HD);
    transpose_rna<<<dim3(FFD / 32, HD / 32),  tb>>>(W1, w1t, HD,  FFD);
    transpose_rna<<<dim3(HD / 32,  FFD / 32), tb>>>(W2, w2t, FFD, HD);

    const dim3 gQKV(3 * HD / 128, BSR / 128);  // (24, 64)
    const dim3 gHd (HD  / 128,    BSR / 128);  // (8, 64)
    const dim3 gFf (FFD / 128,    BSR / 128);  // (32, 64)

    // fused QKV projection + bias + RoPE
    gemm_mma<2><<<gQKV, 128, GEMM_SMEM>>>(x, wqkvt, bqkv, nullptr, q, BSR, HD, HD, k, v);

    // Flash attention on tensor cores -> ctx
    attn_mma<<<dim3(SS / 128, BB * NHH), 256, ATT_SMEM>>>(q, k, v, ctx);

    // O projection + residual(x) -> r1 ; LN -> h
    gemm_mma<0><<<gHd, 128, GEMM_SMEM>>>(ctx, wot, bo, x, r1, BSR, HD, HD);
    ln_kernel<<<BSR, 256>>>(r1, g1, beta1, h);

    // FFN
    gemm_mma<1><<<gFf, 128, GEMM_SMEM>>>(h,  w1t, b1, nullptr, ff, BSR, FFD, HD);
    gemm_mma<0><<<gHd, 128, GEMM_SMEM>>>(ff, w2t, b2, h,       r2, BSR, HD, FFD);

    // final LN -> out
    ln_kernel<<<BSR, 256>>>(r2, g2, beta2, out);
}